// round 7
// baseline (speedup 1.0000x reference)
#include <cuda_runtime.h>
#include <cuda_bf16.h>
#include <math.h>
#include <stdint.h>

// ---------------- problem constants ----------------
#define NB   8
#define NN   4096
#define CVD  256
#define CTD  512
#define NT   77
#define TPAD 96
#define NHH  8
#define DH   32
#define TOPM 5
#define ROWS (NB*NN)
#define FFN  (4*CVD)

// ---------------- scratch ----------------
__device__ float g_x[ROWS*CVD];                               // LN1 fp32 (residual)
__device__ __nv_bfloat16 g_xh[ROWS*CVD], g_xl[ROWS*CVD];      // LN1 split
__device__ float g_q[ROWS*CVD];                               // q (l2-normed)
__device__ float g_kT[NB*NHH*DH*TPAD];
__device__ float g_v[NB*NT*CVD];
__device__ int   g_pad[NB*NT];
__device__ __nv_bfloat16 g_ah[ROWS*CVD], g_al[ROWS*CVD];      // aligned split
__device__ float g_proj[ROWS*CVD];
__device__ float g_y2[ROWS*CVD];                              // LN2 fp32 (residual)
__device__ __nv_bfloat16 g_y2h[ROWS*CVD], g_y2l[ROWS*CVD];    // LN2 split
__device__ __nv_bfloat16 g_hh[ROWS*FFN], g_hl[ROWS*FFN];      // FFN hidden split
// pre-split transposed weights [N][K]
__device__ __nv_bfloat16 g_wqh[CVD*CVD], g_wql[CVD*CVD];
__device__ __nv_bfloat16 g_woh[CVD*CVD], g_wol[CVD*CVD];
__device__ __nv_bfloat16 g_w1h[FFN*CVD], g_w1l[FFN*CVD];
__device__ __nv_bfloat16 g_w2h[CVD*FFN], g_w2l[CVD*FFN];

__device__ __forceinline__ void bf16_split(float x, __nv_bfloat16& h, __nv_bfloat16& l) {
    h = __float2bfloat16_rn(x);
    l = __float2bfloat16_rn(x - __bfloat162float(h));
}

// ---------------- weight split + transpose: W[K][N] fp32 -> Wh/Wl[N][K] bf16 ----------------
__global__ __launch_bounds__(256) void wsplit_kernel(const float* __restrict__ W,
                                                     __nv_bfloat16* __restrict__ Wh,
                                                     __nv_bfloat16* __restrict__ Wl,
                                                     int K, int N) {
    int idx = blockIdx.x * 256 + threadIdx.x;
    int k = idx / N, n = idx - k * N;
    float x = W[idx];
    __nv_bfloat16 h, l; bf16_split(x, h, l);
    Wh[n * K + k] = h;
    Wl[n * K + k] = l;
}

// ---------------- LN1 ----------------
__global__ __launch_bounds__(256) void ln1_kernel(const float* __restrict__ in,
                                                  const float* __restrict__ g,
                                                  const float* __restrict__ b) {
    int warp = (blockIdx.x * blockDim.x + threadIdx.x) >> 5;
    int lane = threadIdx.x & 31;
    const float* row = in + (size_t)warp * CVD;
    float v[8]; float s = 0.f, ss = 0.f;
#pragma unroll
    for (int i = 0; i < 8; i++) { v[i] = row[lane*8 + i]; s += v[i]; ss += v[i]*v[i]; }
#pragma unroll
    for (int o = 16; o; o >>= 1) { s += __shfl_xor_sync(~0u, s, o); ss += __shfl_xor_sync(~0u, ss, o); }
    float mu  = s * (1.f/CVD);
    float inv = rsqrtf(ss * (1.f/CVD) - mu*mu + 1e-5f);
    size_t base = (size_t)warp * CVD;
#pragma unroll
    for (int i = 0; i < 8; i++) {
        int c = lane*8 + i;
        float y = (v[i]-mu)*inv*g[c] + b[c];
        g_x[base + c] = y;
        __nv_bfloat16 h, l; bf16_split(y, h, l);
        g_xh[base + c] = h; g_xl[base + c] = l;
    }
}

// ---------------- LN2 + residual ----------------
__global__ __launch_bounds__(256) void ln2res_kernel(const float* __restrict__ g,
                                                     const float* __restrict__ b,
                                                     const float* __restrict__ alpha_p) {
    int warp = (blockIdx.x * blockDim.x + threadIdx.x) >> 5;
    int lane = threadIdx.x & 31;
    float alpha = alpha_p[0];
    size_t base = (size_t)warp * CVD;
    float v[8]; float s = 0.f, ss = 0.f;
#pragma unroll
    for (int i = 0; i < 8; i++) {
        int c = lane*8 + i;
        v[i] = g_x[base + c] + alpha * g_proj[base + c];
        s += v[i]; ss += v[i]*v[i];
    }
#pragma unroll
    for (int o = 16; o; o >>= 1) { s += __shfl_xor_sync(~0u, s, o); ss += __shfl_xor_sync(~0u, ss, o); }
    float mu  = s * (1.f/CVD);
    float inv = rsqrtf(ss * (1.f/CVD) - mu*mu + 1e-5f);
#pragma unroll
    for (int i = 0; i < 8; i++) {
        int c = lane*8 + i;
        float y = (v[i]-mu)*inv*g[c] + b[c];
        g_y2[base + c] = y;
        __nv_bfloat16 h, l; bf16_split(y, h, l);
        g_y2h[base + c] = h; g_y2l[base + c] = l;
    }
}

// ---------------- K/V projection + pad + k l2norm + transpose ----------------
__global__ __launch_bounds__(256) void kv_kernel(const float* __restrict__ text,
                                                 const float* __restrict__ Wk, const float* __restrict__ bk,
                                                 const float* __restrict__ Wv, const float* __restrict__ bv) {
    int bt = blockIdx.x;
    int b  = bt / NT, t = bt - b * NT;
    int c  = threadIdx.x;
    __shared__ float txt[CTD];
    __shared__ float red[256];
    const float* trow = text + (size_t)bt * CTD;
    txt[c] = trow[c]; txt[c+256] = trow[c+256];
    __syncthreads();
    red[c] = fabsf(txt[c]) + fabsf(txt[c+256]);
    __syncthreads();
    for (int s = 128; s; s >>= 1) { if (c < s) red[c] += red[c+s]; __syncthreads(); }
    if (c == 0) g_pad[bt] = (red[0] <= 1e-6f);
    float kc = bk[c], vc = bv[c];
#pragma unroll 4
    for (int kk = 0; kk < CTD; kk++) {
        float tv = txt[kk];
        kc += tv * Wk[kk*CVD + c];
        vc += tv * Wv[kk*CVD + c];
    }
    float ss = kc * kc;
#pragma unroll
    for (int o = 16; o; o >>= 1) ss += __shfl_xor_sync(~0u, ss, o);
    kc /= fmaxf(sqrtf(ss), 1e-6f);
    int h = c >> 5, d = c & 31;
    g_kT[((b*NHH + h)*DH + d)*TPAD + t] = kc;
    g_v[(size_t)bt*CVD + c] = vc;
}

// ---------------- attention: block per (b,n), warp per head ----------------
__global__ __launch_bounds__(256) void attn_kernel(const float* __restrict__ logit_scale) {
    int row = blockIdx.x;
    int b   = row >> 12;
    int tid = threadIdx.x;
    int h = tid >> 5, lane = tid & 31;
    __shared__ float qs[CVD];
    __shared__ int   spad[NT];
    qs[tid] = g_q[(size_t)row * CVD + tid];
    if (tid < NT) spad[tid] = g_pad[b*NT + tid];
    __syncthreads();

    float ls = logit_scale[0];
    float scale = expf(fminf(fmaxf(ls, -2.f), 2.f)) * 0.17677669529663687f;

    const float* kT = g_kT + ((size_t)(b*NHH + h) * DH) * TPAD;
    float a0 = 0.f, a1 = 0.f, a2 = 0.f;
#pragma unroll
    for (int d = 0; d < DH; d++) {
        float qd = qs[h*DH + d];
        const float* kr = kT + d*TPAD;
        a0 += qd * kr[lane];
        a1 += qd * kr[lane + 32];
        a2 += qd * kr[lane + 64];
    }

    float s[3];
    s[0] = !spad[lane] ? a0 * scale : -INFINITY;
    s[1] = (lane + 32 < NT && !spad[lane + 32]) ? a1 * scale : -INFINITY;
    s[2] = (lane + 64 < NT && !spad[lane + 64]) ? a2 * scale : -INFINITY;

    float topv[TOPM]; int topt[TOPM];
#pragma unroll
    for (int it = 0; it < TOPM; it++) {
        float bv = s[0]; int bt = lane;
        if (s[1] > bv) { bv = s[1]; bt = lane + 32; }
        if (s[2] > bv) { bv = s[2]; bt = lane + 64; }
#pragma unroll
        for (int o = 16; o; o >>= 1) {
            float ov = __shfl_xor_sync(~0u, bv, o);
            int   ot = __shfl_xor_sync(~0u, bt, o);
            if (ov > bv || (ov == bv && ot < bt)) { bv = ov; bt = ot; }
        }
        topv[it] = bv; topt[it] = bt;
        if ((bt & 31) == lane) s[bt >> 5] = -INFINITY;
    }

    float outv = 0.f;
    float m = topv[0];
    if (!(m == -INFINITY)) {
        float e[TOPM]; float ws = 0.f;
#pragma unroll
        for (int i = 0; i < TOPM; i++) { e[i] = expf(topv[i] - m); ws += e[i]; }
        float inv = 1.f / ws;
        const float* vb = g_v + (size_t)b * NT * CVD + h * DH + lane;
#pragma unroll
        for (int i = 0; i < TOPM; i++) outv += (e[i] * inv) * vb[(size_t)topt[i] * CVD];
    }
    size_t oi = (size_t)row * CVD + h*DH + lane;
    __nv_bfloat16 hh, ll; bf16_split(outv, hh, ll);
    g_ah[oi] = hh; g_al[oi] = ll;
}

// ---------------- mma helper ----------------
__device__ __forceinline__ void mma16(float* c, const uint32_t* a, const uint32_t* b) {
    asm volatile("mma.sync.aligned.m16n8k16.row.col.f32.bf16.bf16.f32 "
        "{%0,%1,%2,%3}, {%4,%5,%6,%7}, {%8,%9}, {%0,%1,%2,%3};"
        : "+f"(c[0]), "+f"(c[1]), "+f"(c[2]), "+f"(c[3])
        : "r"(a[0]), "r"(a[1]), "r"(a[2]), "r"(a[3]), "r"(b[0]), "r"(b[1]));
}

// ---------------- split-bf16 GEMM, pre-split operands ----------------
// C[M x N] = (Ah+Al)[M][K] @ (Bh+Bl)[N][K]^T (+bias, epilogue by mode)
// mode: 0 plain fp32, 1 gelu -> bf16 hi/lo, 2 per-32col l2norm fp32, 3 +res fp32.
// Block 128x64, BK=16, 8 warps (4M x 2N), warp 32x32 = 2x4 m16n8k16. Double-buffered smem.
__global__ __launch_bounds__(256) void gemm_split_kernel(
    const __nv_bfloat16* __restrict__ Ahp, const __nv_bfloat16* __restrict__ Alp,
    const __nv_bfloat16* __restrict__ Bhp, const __nv_bfloat16* __restrict__ Blp,
    const float* __restrict__ bias, const float* __restrict__ res,
    float* __restrict__ outF, __nv_bfloat16* __restrict__ outH, __nv_bfloat16* __restrict__ outL,
    int K, int N, int mode)
{
    __shared__ uint32_t Ah[2][8][136], Al[2][8][136];   // [k2][m], stride 136 = 8 mod 32
    __shared__ uint32_t Bh[2][8][72],  Bl[2][8][72];    // [k2][n], stride 72 = 8 mod 32

    int tid  = threadIdx.x;
    int lane = tid & 31, wid = tid >> 5;
    int warpM = wid & 3, warpN = wid >> 2;
    int g = lane >> 2, t4 = lane & 3;
    int m0 = blockIdx.y * 128, n0 = blockIdx.x * 64;
    int mbase = warpM * 32, nbase = warpN * 32;

    float c[2][4][4];
#pragma unroll
    for (int i = 0; i < 2; i++)
#pragma unroll
        for (int j = 0; j < 4; j++)
#pragma unroll
            for (int l = 0; l < 4; l++) c[i][j][l] = 0.f;

    // A loader: row ar, k-half (8 bf16 = 1 uint4 = 4 k2-pairs)
    int ar   = tid >> 1;
    int ha   = tid & 1;            // 0/1 -> k offset 8*ha
    // B loader: col bn, k-quarter (4 bf16 = 1 uint2 = 2 k2-pairs)
    int bn   = tid & 63;
    int kh   = tid >> 6;           // 0..3 -> k offset 4*kh
    const __nv_bfloat16* Aptr_h = Ahp + (size_t)(m0 + ar) * K + 8*ha;
    const __nv_bfloat16* Aptr_l = Alp + (size_t)(m0 + ar) * K + 8*ha;
    const __nv_bfloat16* Bptr_h = Bhp + (size_t)(n0 + bn) * K + 4*kh;
    const __nv_bfloat16* Bptr_l = Blp + (size_t)(n0 + bn) * K + 4*kh;

    uint4 a4h, a4l; uint2 b2h, b2l;
    a4h = *(const uint4*)(Aptr_h);
    a4l = *(const uint4*)(Aptr_l);
    b2h = *(const uint2*)(Bptr_h);
    b2l = *(const uint2*)(Bptr_l);

    // stage tile 0
    {
        int k2a = 4*ha, k2b = 2*kh;
        Ah[0][k2a+0][ar] = a4h.x; Ah[0][k2a+1][ar] = a4h.y; Ah[0][k2a+2][ar] = a4h.z; Ah[0][k2a+3][ar] = a4h.w;
        Al[0][k2a+0][ar] = a4l.x; Al[0][k2a+1][ar] = a4l.y; Al[0][k2a+2][ar] = a4l.z; Al[0][k2a+3][ar] = a4l.w;
        Bh[0][k2b  ][bn] = b2h.x; Bh[0][k2b+1][bn] = b2h.y;
        Bl[0][k2b  ][bn] = b2l.x; Bl[0][k2b+1][bn] = b2l.y;
    }

    int stage = 0;
    for (int k0 = 0; k0 < K; k0 += 16) {
        __syncthreads();
        bool more = (k0 + 16) < K;
        if (more) {
            a4h = *(const uint4*)(Aptr_h + k0 + 16);
            a4l = *(const uint4*)(Aptr_l + k0 + 16);
            b2h = *(const uint2*)(Bptr_h + k0 + 16);
            b2l = *(const uint2*)(Bptr_l + k0 + 16);
        }

        uint32_t ah[2][4], al[2][4], bh[4][2], blo[4][2];
#pragma unroll
        for (int mt = 0; mt < 2; mt++) {
            int r0 = mbase + mt*16 + g;
            ah[mt][0] = Ah[stage][t4  ][r0];   ah[mt][1] = Ah[stage][t4  ][r0+8];
            ah[mt][2] = Ah[stage][t4+4][r0];   ah[mt][3] = Ah[stage][t4+4][r0+8];
            al[mt][0] = Al[stage][t4  ][r0];   al[mt][1] = Al[stage][t4  ][r0+8];
            al[mt][2] = Al[stage][t4+4][r0];   al[mt][3] = Al[stage][t4+4][r0+8];
        }
#pragma unroll
        for (int nt = 0; nt < 4; nt++) {
            int cn = nbase + nt*8 + g;
            bh[nt][0]  = Bh[stage][t4][cn];    bh[nt][1]  = Bh[stage][t4+4][cn];
            blo[nt][0] = Bl[stage][t4][cn];    blo[nt][1] = Bl[stage][t4+4][cn];
        }
#pragma unroll
        for (int mt = 0; mt < 2; mt++)
#pragma unroll
            for (int nt = 0; nt < 4; nt++) {
                mma16(c[mt][nt], al[mt], bh[nt]);
                mma16(c[mt][nt], ah[mt], blo[nt]);
                mma16(c[mt][nt], ah[mt], bh[nt]);
            }

        if (more) {
            int ns = stage ^ 1;
            int k2a = 4*ha, k2b = 2*kh;
            Ah[ns][k2a+0][ar] = a4h.x; Ah[ns][k2a+1][ar] = a4h.y; Ah[ns][k2a+2][ar] = a4h.z; Ah[ns][k2a+3][ar] = a4h.w;
            Al[ns][k2a+0][ar] = a4l.x; Al[ns][k2a+1][ar] = a4l.y; Al[ns][k2a+2][ar] = a4l.z; Al[ns][k2a+3][ar] = a4l.w;
            Bh[ns][k2b  ][bn] = b2h.x; Bh[ns][k2b+1][bn] = b2h.y;
            Bl[ns][k2b  ][bn] = b2l.x; Bl[ns][k2b+1][bn] = b2l.y;
        }
        stage ^= 1;
    }

    // epilogue
#pragma unroll
    for (int mt = 0; mt < 2; mt++)
#pragma unroll
        for (int nt = 0; nt < 4; nt++) {
            int col = n0 + nbase + nt*8 + t4*2;
            float b0v = bias[col], b1v = bias[col + 1];
            c[mt][nt][0] += b0v; c[mt][nt][1] += b1v;
            c[mt][nt][2] += b0v; c[mt][nt][3] += b1v;
        }

    if (mode == 2) {
#pragma unroll
        for (int mt = 0; mt < 2; mt++) {
            float ss0 = 0.f, ss1 = 0.f;
#pragma unroll
            for (int nt = 0; nt < 4; nt++) {
                ss0 += c[mt][nt][0]*c[mt][nt][0] + c[mt][nt][1]*c[mt][nt][1];
                ss1 += c[mt][nt][2]*c[mt][nt][2] + c[mt][nt][3]*c[mt][nt][3];
            }
            ss0 += __shfl_xor_sync(~0u, ss0, 1); ss0 += __shfl_xor_sync(~0u, ss0, 2);
            ss1 += __shfl_xor_sync(~0u, ss1, 1); ss1 += __shfl_xor_sync(~0u, ss1, 2);
            float i0 = 1.f / fmaxf(sqrtf(ss0), 1e-6f);
            float i1 = 1.f / fmaxf(sqrtf(ss1), 1e-6f);
#pragma unroll
            for (int nt = 0; nt < 4; nt++) {
                c[mt][nt][0] *= i0; c[mt][nt][1] *= i0;
                c[mt][nt][2] *= i1; c[mt][nt][3] *= i1;
            }
        }
    }

#pragma unroll
    for (int mt = 0; mt < 2; mt++)
#pragma unroll
        for (int nt = 0; nt < 4; nt++) {
            int col = n0 + nbase + nt*8 + t4*2;
            size_t r0 = (size_t)(m0 + mbase + mt*16 + g);
            size_t r1 = r0 + 8;
            float v0 = c[mt][nt][0], v1 = c[mt][nt][1];
            float v2 = c[mt][nt][2], v3 = c[mt][nt][3];
            if (mode == 1) {
                v0 = 0.5f*v0*(1.f + erff(v0*0.70710678118654752f));
                v1 = 0.5f*v1*(1.f + erff(v1*0.70710678118654752f));
                v2 = 0.5f*v2*(1.f + erff(v2*0.70710678118654752f));
                v3 = 0.5f*v3*(1.f + erff(v3*0.70710678118654752f));
                __nv_bfloat16 h0,l0,h1,l1,h2,l2,h3,l3;
                bf16_split(v0,h0,l0); bf16_split(v1,h1,l1);
                bf16_split(v2,h2,l2); bf16_split(v3,h3,l3);
                __nv_bfloat162 hp0 = __halves2bfloat162(h0,h1), hp1 = __halves2bfloat162(h2,h3);
                __nv_bfloat162 lp0 = __halves2bfloat162(l0,l1), lp1 = __halves2bfloat162(l2,l3);
                *(uint32_t*)&outH[r0*N + col] = *(uint32_t*)&hp0;
                *(uint32_t*)&outL[r0*N + col] = *(uint32_t*)&lp0;
                *(uint32_t*)&outH[r1*N + col] = *(uint32_t*)&hp1;
                *(uint32_t*)&outL[r1*N + col] = *(uint32_t*)&lp1;
            } else {
                if (mode == 3) {
                    v0 += res[r0*N + col]; v1 += res[r0*N + col + 1];
                    v2 += res[r1*N + col]; v3 += res[r1*N + col + 1];
                }
                *(float2*)&outF[r0*N + col] = make_float2(v0, v1);
                *(float2*)&outF[r1*N + col] = make_float2(v2, v3);
            }
        }
}

// ---------------- launch ----------------
extern "C" void kernel_launch(void* const* d_in, const int* in_sizes, int n_in,
                              void* d_out, int out_size) {
    const float* vis   = (const float*)d_in[0];
    const float* text  = (const float*)d_in[1];
    const float* Wq    = (const float*)d_in[2];
    const float* bq    = (const float*)d_in[3];
    const float* Wk    = (const float*)d_in[4];
    const float* bk    = (const float*)d_in[5];
    const float* Wv    = (const float*)d_in[6];
    const float* bv    = (const float*)d_in[7];
    const float* Wo    = (const float*)d_in[8];
    const float* bo    = (const float*)d_in[9];
    const float* g1    = (const float*)d_in[10];
    const float* b1    = (const float*)d_in[11];
    const float* g2    = (const float*)d_in[12];
    const float* b2    = (const float*)d_in[13];
    const float* Wf1   = (const float*)d_in[14];
    const float* bf1   = (const float*)d_in[15];
    const float* Wf2   = (const float*)d_in[16];
    const float* bf2   = (const float*)d_in[17];
    const float* ls    = (const float*)d_in[18];
    const float* alpha = (const float*)d_in[19];
    float* out = (float*)d_out;

    __nv_bfloat16 *pxh, *pxl, *pah, *pal, *py2h, *py2l, *phh, *phl;
    __nv_bfloat16 *pwqh, *pwql, *pwoh, *pwol, *pw1h, *pw1l, *pw2h, *pw2l;
    float *pq, *pproj, *py2;
    cudaGetSymbolAddress((void**)&pxh,  g_xh);  cudaGetSymbolAddress((void**)&pxl,  g_xl);
    cudaGetSymbolAddress((void**)&pah,  g_ah);  cudaGetSymbolAddress((void**)&pal,  g_al);
    cudaGetSymbolAddress((void**)&py2h, g_y2h); cudaGetSymbolAddress((void**)&py2l, g_y2l);
    cudaGetSymbolAddress((void**)&phh,  g_hh);  cudaGetSymbolAddress((void**)&phl,  g_hl);
    cudaGetSymbolAddress((void**)&pwqh, g_wqh); cudaGetSymbolAddress((void**)&pwql, g_wql);
    cudaGetSymbolAddress((void**)&pwoh, g_woh); cudaGetSymbolAddress((void**)&pwol, g_wol);
    cudaGetSymbolAddress((void**)&pw1h, g_w1h); cudaGetSymbolAddress((void**)&pw1l, g_w1l);
    cudaGetSymbolAddress((void**)&pw2h, g_w2h); cudaGetSymbolAddress((void**)&pw2l, g_w2l);
    cudaGetSymbolAddress((void**)&pq,   g_q);
    cudaGetSymbolAddress((void**)&pproj,g_proj);
    cudaGetSymbolAddress((void**)&py2,  g_y2);

    // one-time-per-call weight split + transpose (cheap: 786K elems)
    wsplit_kernel<<<CVD*CVD/256, 256>>>(Wq,  pwqh, pwql, CVD, CVD);
    wsplit_kernel<<<CVD*CVD/256, 256>>>(Wo,  pwoh, pwol, CVD, CVD);
    wsplit_kernel<<<CVD*FFN/256, 256>>>(Wf1, pw1h, pw1l, CVD, FFN);
    wsplit_kernel<<<CVD*FFN/256, 256>>>(Wf2, pw2h, pw2l, FFN, CVD);

    ln1_kernel<<<ROWS/8, 256>>>(vis, g1, b1);
    kv_kernel<<<NB*NT, 256>>>(text, Wk, bk, Wv, bv);

    // q = l2norm_per_head(x @ Wq + bq)
    gemm_split_kernel<<<dim3(CVD/64, ROWS/128), 256>>>(
        pxh, pxl, pwqh, pwql, bq, nullptr, pq, nullptr, nullptr, CVD, CVD, 2);
    attn_kernel<<<ROWS, 256>>>(ls);
    // proj = aligned @ Wo + bo
    gemm_split_kernel<<<dim3(CVD/64, ROWS/128), 256>>>(
        pah, pal, pwoh, pwol, bo, nullptr, pproj, nullptr, nullptr, CVD, CVD, 0);
    ln2res_kernel<<<ROWS/8, 256>>>(g2, b2, alpha);
    // hdn = gelu(y2 @ Wf1 + bf1) -> bf16 hi/lo
    gemm_split_kernel<<<dim3(FFN/64, ROWS/128), 256>>>(
        py2h, py2l, pw1h, pw1l, bf1, nullptr, nullptr, phh, phl, CVD, FFN, 1);
    // out = y2 + hdn @ Wf2 + bf2
    gemm_split_kernel<<<dim3(CVD/64, ROWS/128), 256>>>(
        phh, phl, pw2h, pw2l, bf2, py2, out, nullptr, nullptr, FFN, CVD, 3);
}

// round 8
// speedup vs baseline: 1.3451x; 1.3451x over previous
#include <cuda_runtime.h>
#include <cuda_bf16.h>
#include <math.h>
#include <stdint.h>

// ---------------- problem constants ----------------
#define NB   8
#define NN   4096
#define CVD  256
#define CTD  512
#define NT   77
#define TPAD 96
#define NHH  8
#define DH   32
#define TOPM 5
#define ROWS (NB*NN)
#define FFN  (4*CVD)

// ---------------- scratch ----------------
__device__ float g_x[ROWS*CVD];                               // LN1 fp32 (residual)
__device__ __nv_bfloat16 g_xh[ROWS*CVD], g_xl[ROWS*CVD];      // LN1 split (row-major, k-contig)
__device__ float g_q[ROWS*CVD];                               // q (l2-normed)
__device__ float g_kT[NB*NHH*DH*TPAD];
__device__ float g_v[NB*NT*CVD];
__device__ int   g_pad[NB*NT];
__device__ __nv_bfloat16 g_ah[ROWS*CVD], g_al[ROWS*CVD];      // aligned split
__device__ float g_proj[ROWS*CVD];
__device__ float g_y2[ROWS*CVD];                              // LN2 fp32 (residual)
__device__ __nv_bfloat16 g_y2h[ROWS*CVD], g_y2l[ROWS*CVD];    // LN2 split
__device__ __nv_bfloat16 g_hh[ROWS*FFN], g_hl[ROWS*FFN];      // FFN hidden split
// pre-split weights, k-pair-packed bf16x2, layout [K/2][N] (n-contiguous -> coalesced B loads)
__device__ uint32_t g_wqh[(CVD/2)*CVD], g_wql[(CVD/2)*CVD];
__device__ uint32_t g_woh[(CVD/2)*CVD], g_wol[(CVD/2)*CVD];
__device__ uint32_t g_w1h[(CVD/2)*FFN], g_w1l[(CVD/2)*FFN];
__device__ uint32_t g_w2h[(FFN/2)*CVD], g_w2l[(FFN/2)*CVD];

__device__ __forceinline__ void bf16_split(float x, __nv_bfloat16& h, __nv_bfloat16& l) {
    h = __float2bfloat16_rn(x);
    l = __float2bfloat16_rn(x - __bfloat162float(h));
}

// ---------------- weight split + pack: W[K][N] fp32 -> Wh/Wl[K/2][N] bf16x2 ----------------
__global__ __launch_bounds__(256) void wsplit_kernel(const float* __restrict__ W,
                                                     uint32_t* __restrict__ Wh,
                                                     uint32_t* __restrict__ Wl,
                                                     int N) {
    int idx = blockIdx.x * 256 + threadIdx.x;       // over (K/2)*N
    int k2 = idx / N, n = idx - k2 * N;
    float x0 = W[(2*k2    ) * N + n];
    float x1 = W[(2*k2 + 1) * N + n];
    __nv_bfloat16 h0, l0, h1, l1;
    bf16_split(x0, h0, l0); bf16_split(x1, h1, l1);
    Wh[idx] = (uint32_t)__bfloat16_as_ushort(h0) | ((uint32_t)__bfloat16_as_ushort(h1) << 16);
    Wl[idx] = (uint32_t)__bfloat16_as_ushort(l0) | ((uint32_t)__bfloat16_as_ushort(l1) << 16);
}

// ---------------- LN1 ----------------
__global__ __launch_bounds__(256) void ln1_kernel(const float* __restrict__ in,
                                                  const float* __restrict__ g,
                                                  const float* __restrict__ b) {
    int warp = (blockIdx.x * blockDim.x + threadIdx.x) >> 5;
    int lane = threadIdx.x & 31;
    const float* row = in + (size_t)warp * CVD;
    float v[8]; float s = 0.f, ss = 0.f;
#pragma unroll
    for (int i = 0; i < 8; i++) { v[i] = row[lane*8 + i]; s += v[i]; ss += v[i]*v[i]; }
#pragma unroll
    for (int o = 16; o; o >>= 1) { s += __shfl_xor_sync(~0u, s, o); ss += __shfl_xor_sync(~0u, ss, o); }
    float mu  = s * (1.f/CVD);
    float inv = rsqrtf(ss * (1.f/CVD) - mu*mu + 1e-5f);
    size_t base = (size_t)warp * CVD;
#pragma unroll
    for (int i = 0; i < 8; i++) {
        int c = lane*8 + i;
        float y = (v[i]-mu)*inv*g[c] + b[c];
        g_x[base + c] = y;
        __nv_bfloat16 h, l; bf16_split(y, h, l);
        g_xh[base + c] = h; g_xl[base + c] = l;
    }
}

// ---------------- LN2 + residual ----------------
__global__ __launch_bounds__(256) void ln2res_kernel(const float* __restrict__ g,
                                                     const float* __restrict__ b,
                                                     const float* __restrict__ alpha_p) {
    int warp = (blockIdx.x * blockDim.x + threadIdx.x) >> 5;
    int lane = threadIdx.x & 31;
    float alpha = alpha_p[0];
    size_t base = (size_t)warp * CVD;
    float v[8]; float s = 0.f, ss = 0.f;
#pragma unroll
    for (int i = 0; i < 8; i++) {
        int c = lane*8 + i;
        v[i] = g_x[base + c] + alpha * g_proj[base + c];
        s += v[i]; ss += v[i]*v[i];
    }
#pragma unroll
    for (int o = 16; o; o >>= 1) { s += __shfl_xor_sync(~0u, s, o); ss += __shfl_xor_sync(~0u, ss, o); }
    float mu  = s * (1.f/CVD);
    float inv = rsqrtf(ss * (1.f/CVD) - mu*mu + 1e-5f);
#pragma unroll
    for (int i = 0; i < 8; i++) {
        int c = lane*8 + i;
        float y = (v[i]-mu)*inv*g[c] + b[c];
        g_y2[base + c] = y;
        __nv_bfloat16 h, l; bf16_split(y, h, l);
        g_y2h[base + c] = h; g_y2l[base + c] = l;
    }
}

// ---------------- K/V projection + pad + k l2norm + transpose ----------------
__global__ __launch_bounds__(256) void kv_kernel(const float* __restrict__ text,
                                                 const float* __restrict__ Wk, const float* __restrict__ bk,
                                                 const float* __restrict__ Wv, const float* __restrict__ bv) {
    int bt = blockIdx.x;
    int b  = bt / NT, t = bt - b * NT;
    int c  = threadIdx.x;
    __shared__ float txt[CTD];
    __shared__ float red[256];
    const float* trow = text + (size_t)bt * CTD;
    txt[c] = trow[c]; txt[c+256] = trow[c+256];
    __syncthreads();
    red[c] = fabsf(txt[c]) + fabsf(txt[c+256]);
    __syncthreads();
    for (int s = 128; s; s >>= 1) { if (c < s) red[c] += red[c+s]; __syncthreads(); }
    if (c == 0) g_pad[bt] = (red[0] <= 1e-6f);
    float kc = bk[c], vc = bv[c];
#pragma unroll 4
    for (int kk = 0; kk < CTD; kk++) {
        float tv = txt[kk];
        kc += tv * Wk[kk*CVD + c];
        vc += tv * Wv[kk*CVD + c];
    }
    float ss = kc * kc;
#pragma unroll
    for (int o = 16; o; o >>= 1) ss += __shfl_xor_sync(~0u, ss, o);
    kc /= fmaxf(sqrtf(ss), 1e-6f);
    int h = c >> 5, d = c & 31;
    g_kT[((b*NHH + h)*DH + d)*TPAD + t] = kc;
    g_v[(size_t)bt*CVD + c] = vc;
}

// ---------------- attention: block per (b,n), warp per head ----------------
__global__ __launch_bounds__(256) void attn_kernel(const float* __restrict__ logit_scale) {
    int row = blockIdx.x;
    int b   = row >> 12;
    int tid = threadIdx.x;
    int h = tid >> 5, lane = tid & 31;
    __shared__ float qs[CVD];
    __shared__ int   spad[NT];
    qs[tid] = g_q[(size_t)row * CVD + tid];
    if (tid < NT) spad[tid] = g_pad[b*NT + tid];
    __syncthreads();

    float ls = logit_scale[0];
    float scale = expf(fminf(fmaxf(ls, -2.f), 2.f)) * 0.17677669529663687f;

    const float* kT = g_kT + ((size_t)(b*NHH + h) * DH) * TPAD;
    float a0 = 0.f, a1 = 0.f, a2 = 0.f;
#pragma unroll
    for (int d = 0; d < DH; d++) {
        float qd = qs[h*DH + d];
        const float* kr = kT + d*TPAD;
        a0 += qd * kr[lane];
        a1 += qd * kr[lane + 32];
        a2 += qd * kr[lane + 64];
    }

    float s[3];
    s[0] = !spad[lane] ? a0 * scale : -INFINITY;
    s[1] = (lane + 32 < NT && !spad[lane + 32]) ? a1 * scale : -INFINITY;
    s[2] = (lane + 64 < NT && !spad[lane + 64]) ? a2 * scale : -INFINITY;

    float topv[TOPM]; int topt[TOPM];
#pragma unroll
    for (int it = 0; it < TOPM; it++) {
        float bv = s[0]; int bt = lane;
        if (s[1] > bv) { bv = s[1]; bt = lane + 32; }
        if (s[2] > bv) { bv = s[2]; bt = lane + 64; }
#pragma unroll
        for (int o = 16; o; o >>= 1) {
            float ov = __shfl_xor_sync(~0u, bv, o);
            int   ot = __shfl_xor_sync(~0u, bt, o);
            if (ov > bv || (ov == bv && ot < bt)) { bv = ov; bt = ot; }
        }
        topv[it] = bv; topt[it] = bt;
        if ((bt & 31) == lane) s[bt >> 5] = -INFINITY;
    }

    float outv = 0.f;
    float m = topv[0];
    if (!(m == -INFINITY)) {
        float e[TOPM]; float ws = 0.f;
#pragma unroll
        for (int i = 0; i < TOPM; i++) { e[i] = expf(topv[i] - m); ws += e[i]; }
        float inv = 1.f / ws;
        const float* vb = g_v + (size_t)b * NT * CVD + h * DH + lane;
#pragma unroll
        for (int i = 0; i < TOPM; i++) outv += (e[i] * inv) * vb[(size_t)topt[i] * CVD];
    }
    size_t oi = (size_t)row * CVD + h*DH + lane;
    __nv_bfloat16 hh, ll; bf16_split(outv, hh, ll);
    g_ah[oi] = hh; g_al[oi] = ll;
}

// ---------------- mma helper ----------------
__device__ __forceinline__ void mma16(float* c, const uint32_t* a, const uint32_t* b) {
    asm volatile("mma.sync.aligned.m16n8k16.row.col.f32.bf16.bf16.f32 "
        "{%0,%1,%2,%3}, {%4,%5,%6,%7}, {%8,%9}, {%0,%1,%2,%3};"
        : "+f"(c[0]), "+f"(c[1]), "+f"(c[2]), "+f"(c[3])
        : "r"(a[0]), "r"(a[1]), "r"(a[2]), "r"(a[3]), "r"(b[0]), "r"(b[1]));
}

// ---------------- split-bf16 GEMM, pre-split pre-packed operands ----------------
// C[M x N] = (Ah+Al)[M][K] @ W  where W given as packed [K/2][N] bf16x2 hi/lo.
// mode: 0 plain fp32, 1 gelu -> bf16 hi/lo, 2 per-32col l2norm fp32, 3 +res fp32.
// Block 128x64, BK=16, 8 warps (4M x 2N), warp 32x32 = 2x4 m16n8k16. Double-buffered smem.
__global__ __launch_bounds__(256) void gemm_split_kernel(
    const __nv_bfloat16* __restrict__ Ahp, const __nv_bfloat16* __restrict__ Alp,
    const uint32_t* __restrict__ Bhp, const uint32_t* __restrict__ Blp,
    const float* __restrict__ bias, const float* __restrict__ res,
    float* __restrict__ outF, __nv_bfloat16* __restrict__ outH, __nv_bfloat16* __restrict__ outL,
    int K, int N, int mode)
{
    __shared__ uint32_t Ah[2][8][136], Al[2][8][136];   // [k2][m], stride 136 = 8 mod 32
    __shared__ uint32_t Bh[2][8][72],  Bl[2][8][72];    // [k2][n], stride 72 = 8 mod 32

    int tid  = threadIdx.x;
    int lane = tid & 31, wid = tid >> 5;
    int warpM = wid & 3, warpN = wid >> 2;
    int g = lane >> 2, t4 = lane & 3;
    int m0 = blockIdx.y * 128, n0 = blockIdx.x * 64;
    int mbase = warpM * 32, nbase = warpN * 32;

    float c[2][4][4];
#pragma unroll
    for (int i = 0; i < 2; i++)
#pragma unroll
        for (int j = 0; j < 4; j++)
#pragma unroll
            for (int l = 0; l < 4; l++) c[i][j][l] = 0.f;

    // A loader: row ar (0..127), k-half ha (8 bf16 = uint4 = 4 packed pairs)
    int ar = tid >> 1;
    int ha = tid & 1;
    // B loader: col bn, pair-rows r2, r2+1 (one uint32 each)
    int bn = tid & 63;
    int r2 = (tid >> 6) * 2;
    const __nv_bfloat16* Aptr_h = Ahp + (size_t)(m0 + ar) * K + 8*ha;
    const __nv_bfloat16* Aptr_l = Alp + (size_t)(m0 + ar) * K + 8*ha;
    const uint32_t* Bptr_h = Bhp + (size_t)r2 * N + n0 + bn;
    const uint32_t* Bptr_l = Blp + (size_t)r2 * N + n0 + bn;

    uint4 a4h, a4l;
    uint32_t bh0, bh1, bl0, bl1;
    a4h = *(const uint4*)(Aptr_h);
    a4l = *(const uint4*)(Aptr_l);
    bh0 = Bptr_h[0]; bh1 = Bptr_h[N];
    bl0 = Bptr_l[0]; bl1 = Bptr_l[N];

    // stage tile 0
    {
        int k2a = 4*ha;
        Ah[0][k2a+0][ar] = a4h.x; Ah[0][k2a+1][ar] = a4h.y; Ah[0][k2a+2][ar] = a4h.z; Ah[0][k2a+3][ar] = a4h.w;
        Al[0][k2a+0][ar] = a4l.x; Al[0][k2a+1][ar] = a4l.y; Al[0][k2a+2][ar] = a4l.z; Al[0][k2a+3][ar] = a4l.w;
        Bh[0][r2  ][bn] = bh0; Bh[0][r2+1][bn] = bh1;
        Bl[0][r2  ][bn] = bl0; Bl[0][r2+1][bn] = bl1;
    }

    int stage = 0;
    for (int k0 = 0; k0 < K; k0 += 16) {
        __syncthreads();
        bool more = (k0 + 16) < K;
        if (more) {
            a4h = *(const uint4*)(Aptr_h + k0 + 16);
            a4l = *(const uint4*)(Aptr_l + k0 + 16);
            const uint32_t* bph = Bptr_h + (size_t)(k0/2 + 8) * N;
            const uint32_t* bpl = Bptr_l + (size_t)(k0/2 + 8) * N;
            bh0 = bph[0]; bh1 = bph[N];
            bl0 = bpl[0]; bl1 = bpl[N];
        }

        uint32_t ah[2][4], al[2][4], bh[4][2], blo[4][2];
#pragma unroll
        for (int mt = 0; mt < 2; mt++) {
            int r0 = mbase + mt*16 + g;
            ah[mt][0] = Ah[stage][t4  ][r0];   ah[mt][1] = Ah[stage][t4  ][r0+8];
            ah[mt][2] = Ah[stage][t4+4][r0];   ah[mt][3] = Ah[stage][t4+4][r0+8];
            al[mt][0] = Al[stage][t4  ][r0];   al[mt][1] = Al[stage][t4  ][r0+8];
            al[mt][2] = Al[stage][t4+4][r0];   al[mt][3] = Al[stage][t4+4][r0+8];
        }
#pragma unroll
        for (int nt = 0; nt < 4; nt++) {
            int cn = nbase + nt*8 + g;
            bh[nt][0]  = Bh[stage][t4][cn];    bh[nt][1]  = Bh[stage][t4+4][cn];
            blo[nt][0] = Bl[stage][t4][cn];    blo[nt][1] = Bl[stage][t4+4][cn];
        }
#pragma unroll
        for (int mt = 0; mt < 2; mt++)
#pragma unroll
            for (int nt = 0; nt < 4; nt++) {
                mma16(c[mt][nt], al[mt], bh[nt]);
                mma16(c[mt][nt], ah[mt], blo[nt]);
                mma16(c[mt][nt], ah[mt], bh[nt]);
            }

        if (more) {
            int ns = stage ^ 1;
            int k2a = 4*ha;
            Ah[ns][k2a+0][ar] = a4h.x; Ah[ns][k2a+1][ar] = a4h.y; Ah[ns][k2a+2][ar] = a4h.z; Ah[ns][k2a+3][ar] = a4h.w;
            Al[ns][k2a+0][ar] = a4l.x; Al[ns][k2a+1][ar] = a4l.y; Al[ns][k2a+2][ar] = a4l.z; Al[ns][k2a+3][ar] = a4l.w;
            Bh[ns][r2  ][bn] = bh0; Bh[ns][r2+1][bn] = bh1;
            Bl[ns][r2  ][bn] = bl0; Bl[ns][r2+1][bn] = bl1;
        }
        stage ^= 1;
    }

    // epilogue
#pragma unroll
    for (int mt = 0; mt < 2; mt++)
#pragma unroll
        for (int nt = 0; nt < 4; nt++) {
            int col = n0 + nbase + nt*8 + t4*2;
            float b0v = bias[col], b1v = bias[col + 1];
            c[mt][nt][0] += b0v; c[mt][nt][1] += b1v;
            c[mt][nt][2] += b0v; c[mt][nt][3] += b1v;
        }

    if (mode == 2) {
#pragma unroll
        for (int mt = 0; mt < 2; mt++) {
            float ss0 = 0.f, ss1 = 0.f;
#pragma unroll
            for (int nt = 0; nt < 4; nt++) {
                ss0 += c[mt][nt][0]*c[mt][nt][0] + c[mt][nt][1]*c[mt][nt][1];
                ss1 += c[mt][nt][2]*c[mt][nt][2] + c[mt][nt][3]*c[mt][nt][3];
            }
            ss0 += __shfl_xor_sync(~0u, ss0, 1); ss0 += __shfl_xor_sync(~0u, ss0, 2);
            ss1 += __shfl_xor_sync(~0u, ss1, 1); ss1 += __shfl_xor_sync(~0u, ss1, 2);
            float i0 = 1.f / fmaxf(sqrtf(ss0), 1e-6f);
            float i1 = 1.f / fmaxf(sqrtf(ss1), 1e-6f);
#pragma unroll
            for (int nt = 0; nt < 4; nt++) {
                c[mt][nt][0] *= i0; c[mt][nt][1] *= i0;
                c[mt][nt][2] *= i1; c[mt][nt][3] *= i1;
            }
        }
    }

#pragma unroll
    for (int mt = 0; mt < 2; mt++)
#pragma unroll
        for (int nt = 0; nt < 4; nt++) {
            int col = n0 + nbase + nt*8 + t4*2;
            size_t r0 = (size_t)(m0 + mbase + mt*16 + g);
            size_t r1 = r0 + 8;
            float v0 = c[mt][nt][0], v1 = c[mt][nt][1];
            float v2 = c[mt][nt][2], v3 = c[mt][nt][3];
            if (mode == 1) {
                v0 = 0.5f*v0*(1.f + erff(v0*0.70710678118654752f));
                v1 = 0.5f*v1*(1.f + erff(v1*0.70710678118654752f));
                v2 = 0.5f*v2*(1.f + erff(v2*0.70710678118654752f));
                v3 = 0.5f*v3*(1.f + erff(v3*0.70710678118654752f));
                __nv_bfloat16 h0,l0,h1,l1,h2,l2,h3,l3;
                bf16_split(v0,h0,l0); bf16_split(v1,h1,l1);
                bf16_split(v2,h2,l2); bf16_split(v3,h3,l3);
                __nv_bfloat162 hp0 = __halves2bfloat162(h0,h1), hp1 = __halves2bfloat162(h2,h3);
                __nv_bfloat162 lp0 = __halves2bfloat162(l0,l1), lp1 = __halves2bfloat162(l2,l3);
                *(uint32_t*)&outH[r0*N + col] = *(uint32_t*)&hp0;
                *(uint32_t*)&outL[r0*N + col] = *(uint32_t*)&lp0;
                *(uint32_t*)&outH[r1*N + col] = *(uint32_t*)&hp1;
                *(uint32_t*)&outL[r1*N + col] = *(uint32_t*)&lp1;
            } else {
                if (mode == 3) {
                    v0 += res[r0*N + col]; v1 += res[r0*N + col + 1];
                    v2 += res[r1*N + col]; v3 += res[r1*N + col + 1];
                }
                *(float2*)&outF[r0*N + col] = make_float2(v0, v1);
                *(float2*)&outF[r1*N + col] = make_float2(v2, v3);
            }
        }
}

// ---------------- launch ----------------
extern "C" void kernel_launch(void* const* d_in, const int* in_sizes, int n_in,
                              void* d_out, int out_size) {
    const float* vis   = (const float*)d_in[0];
    const float* text  = (const float*)d_in[1];
    const float* Wq    = (const float*)d_in[2];
    const float* bq    = (const float*)d_in[3];
    const float* Wk    = (const float*)d_in[4];
    const float* bk    = (const float*)d_in[5];
    const float* Wv    = (const float*)d_in[6];
    const float* bv    = (const float*)d_in[7];
    const float* Wo    = (const float*)d_in[8];
    const float* bo    = (const float*)d_in[9];
    const float* g1    = (const float*)d_in[10];
    const float* b1    = (const float*)d_in[11];
    const float* g2    = (const float*)d_in[12];
    const float* b2    = (const float*)d_in[13];
    const float* Wf1   = (const float*)d_in[14];
    const float* bf1   = (const float*)d_in[15];
    const float* Wf2   = (const float*)d_in[16];
    const float* bf2   = (const float*)d_in[17];
    const float* ls    = (const float*)d_in[18];
    const float* alpha = (const float*)d_in[19];
    float* out = (float*)d_out;

    __nv_bfloat16 *pxh, *pxl, *pah, *pal, *py2h, *py2l, *phh, *phl;
    uint32_t *pwqh, *pwql, *pwoh, *pwol, *pw1h, *pw1l, *pw2h, *pw2l;
    float *pq, *pproj, *py2;
    cudaGetSymbolAddress((void**)&pxh,  g_xh);  cudaGetSymbolAddress((void**)&pxl,  g_xl);
    cudaGetSymbolAddress((void**)&pah,  g_ah);  cudaGetSymbolAddress((void**)&pal,  g_al);
    cudaGetSymbolAddress((void**)&py2h, g_y2h); cudaGetSymbolAddress((void**)&py2l, g_y2l);
    cudaGetSymbolAddress((void**)&phh,  g_hh);  cudaGetSymbolAddress((void**)&phl,  g_hl);
    cudaGetSymbolAddress((void**)&pwqh, g_wqh); cudaGetSymbolAddress((void**)&pwql, g_wql);
    cudaGetSymbolAddress((void**)&pwoh, g_woh); cudaGetSymbolAddress((void**)&pwol, g_wol);
    cudaGetSymbolAddress((void**)&pw1h, g_w1h); cudaGetSymbolAddress((void**)&pw1l, g_w1l);
    cudaGetSymbolAddress((void**)&pw2h, g_w2h); cudaGetSymbolAddress((void**)&pw2l, g_w2l);
    cudaGetSymbolAddress((void**)&pq,   g_q);
    cudaGetSymbolAddress((void**)&pproj,g_proj);
    cudaGetSymbolAddress((void**)&py2,  g_y2);

    // weight split + k-pair pack (layout preserved: [K/2][N], coalesced)
    wsplit_kernel<<<(CVD/2)*CVD/256, 256>>>(Wq,  pwqh, pwql, CVD);
    wsplit_kernel<<<(CVD/2)*CVD/256, 256>>>(Wo,  pwoh, pwol, CVD);
    wsplit_kernel<<<(CVD/2)*FFN/256, 256>>>(Wf1, pw1h, pw1l, FFN);
    wsplit_kernel<<<(FFN/2)*CVD/256, 256>>>(Wf2, pw2h, pw2l, CVD);

    ln1_kernel<<<ROWS/8, 256>>>(vis, g1, b1);
    kv_kernel<<<NB*NT, 256>>>(text, Wk, bk, Wv, bv);

    // q = l2norm_per_head(x @ Wq + bq)
    gemm_split_kernel<<<dim3(CVD/64, ROWS/128), 256>>>(
        pxh, pxl, pwqh, pwql, bq, nullptr, pq, nullptr, nullptr, CVD, CVD, 2);
    attn_kernel<<<ROWS, 256>>>(ls);
    // proj = aligned @ Wo + bo
    gemm_split_kernel<<<dim3(CVD/64, ROWS/128), 256>>>(
        pah, pal, pwoh, pwol, bo, nullptr, pproj, nullptr, nullptr, CVD, CVD, 0);
    ln2res_kernel<<<ROWS/8, 256>>>(g2, b2, alpha);
    // hdn = gelu(y2 @ Wf1 + bf1) -> bf16 hi/lo
    gemm_split_kernel<<<dim3(FFN/64, ROWS/128), 256>>>(
        py2h, py2l, pw1h, pw1l, bf1, nullptr, nullptr, phh, phl, CVD, FFN, 1);
    // out = y2 + hdn @ Wf2 + bf2
    gemm_split_kernel<<<dim3(CVD/64, ROWS/128), 256>>>(
        phh, phl, pw2h, pw2l, bf2, py2, out, nullptr, nullptr, FFN, CVD, 3);
}

// round 9
// speedup vs baseline: 1.4244x; 1.0589x over previous
#include <cuda_runtime.h>
#include <cuda_bf16.h>
#include <math.h>
#include <stdint.h>

// ---------------- problem constants ----------------
#define NB   8
#define NN   4096
#define CVD  256
#define CTD  512
#define NT   77
#define TPAD 96
#define NHH  8
#define DH   32
#define TOPM 5
#define ROWS (NB*NN)
#define FFN  (4*CVD)

// ---------------- scratch ----------------
__device__ float g_x[ROWS*CVD];
__device__ __nv_bfloat16 g_xh[ROWS*CVD], g_xl[ROWS*CVD];
__device__ float g_q[ROWS*CVD];
__device__ float g_kT[NB*NHH*DH*TPAD];
__device__ float g_v[NB*NT*CVD];
__device__ int   g_pad[NB*NT];
__device__ __nv_bfloat16 g_ah[ROWS*CVD], g_al[ROWS*CVD];
__device__ float g_proj[ROWS*CVD];
__device__ float g_y2[ROWS*CVD];
__device__ __nv_bfloat16 g_y2h[ROWS*CVD], g_y2l[ROWS*CVD];
__device__ __nv_bfloat16 g_hh[ROWS*FFN], g_hl[ROWS*FFN];
// pre-split weights, k-pair-packed bf16x2, layout [K/2][N]
__device__ uint32_t g_wqh[(CVD/2)*CVD], g_wql[(CVD/2)*CVD];
__device__ uint32_t g_woh[(CVD/2)*CVD], g_wol[(CVD/2)*CVD];
__device__ uint32_t g_w1h[(CVD/2)*FFN], g_w1l[(CVD/2)*FFN];
__device__ uint32_t g_w2h[(FFN/2)*CVD], g_w2l[(FFN/2)*CVD];

__device__ __forceinline__ void bf16_split(float x, __nv_bfloat16& h, __nv_bfloat16& l) {
    h = __float2bfloat16_rn(x);
    l = __float2bfloat16_rn(x - __bfloat162float(h));
}

// ---------------- weight split + pack: W[K][N] fp32 -> Wh/Wl[K/2][N] bf16x2 ----------------
__global__ __launch_bounds__(256) void wsplit_kernel(const float* __restrict__ W,
                                                     uint32_t* __restrict__ Wh,
                                                     uint32_t* __restrict__ Wl,
                                                     int N) {
    int idx = blockIdx.x * 256 + threadIdx.x;
    int k2 = idx / N, n = idx - k2 * N;
    float x0 = W[(2*k2    ) * N + n];
    float x1 = W[(2*k2 + 1) * N + n];
    __nv_bfloat16 h0, l0, h1, l1;
    bf16_split(x0, h0, l0); bf16_split(x1, h1, l1);
    Wh[idx] = (uint32_t)__bfloat16_as_ushort(h0) | ((uint32_t)__bfloat16_as_ushort(h1) << 16);
    Wl[idx] = (uint32_t)__bfloat16_as_ushort(l0) | ((uint32_t)__bfloat16_as_ushort(l1) << 16);
}

// ---------------- LN1 ----------------
__global__ __launch_bounds__(256) void ln1_kernel(const float* __restrict__ in,
                                                  const float* __restrict__ g,
                                                  const float* __restrict__ b) {
    int warp = (blockIdx.x * blockDim.x + threadIdx.x) >> 5;
    int lane = threadIdx.x & 31;
    const float* row = in + (size_t)warp * CVD;
    float v[8]; float s = 0.f, ss = 0.f;
#pragma unroll
    for (int i = 0; i < 8; i++) { v[i] = row[lane*8 + i]; s += v[i]; ss += v[i]*v[i]; }
#pragma unroll
    for (int o = 16; o; o >>= 1) { s += __shfl_xor_sync(~0u, s, o); ss += __shfl_xor_sync(~0u, ss, o); }
    float mu  = s * (1.f/CVD);
    float inv = rsqrtf(ss * (1.f/CVD) - mu*mu + 1e-5f);
    size_t base = (size_t)warp * CVD;
#pragma unroll
    for (int i = 0; i < 8; i++) {
        int c = lane*8 + i;
        float y = (v[i]-mu)*inv*g[c] + b[c];
        g_x[base + c] = y;
        __nv_bfloat16 h, l; bf16_split(y, h, l);
        g_xh[base + c] = h; g_xl[base + c] = l;
    }
}

// ---------------- LN2 + residual ----------------
__global__ __launch_bounds__(256) void ln2res_kernel(const float* __restrict__ g,
                                                     const float* __restrict__ b,
                                                     const float* __restrict__ alpha_p) {
    int warp = (blockIdx.x * blockDim.x + threadIdx.x) >> 5;
    int lane = threadIdx.x & 31;
    float alpha = alpha_p[0];
    size_t base = (size_t)warp * CVD;
    float v[8]; float s = 0.f, ss = 0.f;
#pragma unroll
    for (int i = 0; i < 8; i++) {
        int c = lane*8 + i;
        v[i] = g_x[base + c] + alpha * g_proj[base + c];
        s += v[i]; ss += v[i]*v[i];
    }
#pragma unroll
    for (int o = 16; o; o >>= 1) { s += __shfl_xor_sync(~0u, s, o); ss += __shfl_xor_sync(~0u, ss, o); }
    float mu  = s * (1.f/CVD);
    float inv = rsqrtf(ss * (1.f/CVD) - mu*mu + 1e-5f);
#pragma unroll
    for (int i = 0; i < 8; i++) {
        int c = lane*8 + i;
        float y = (v[i]-mu)*inv*g[c] + b[c];
        g_y2[base + c] = y;
        __nv_bfloat16 h, l; bf16_split(y, h, l);
        g_y2h[base + c] = h; g_y2l[base + c] = l;
    }
}

// ---------------- K/V projection + pad + k l2norm + transpose ----------------
__global__ __launch_bounds__(256) void kv_kernel(const float* __restrict__ text,
                                                 const float* __restrict__ Wk, const float* __restrict__ bk,
                                                 const float* __restrict__ Wv, const float* __restrict__ bv) {
    int bt = blockIdx.x;
    int b  = bt / NT, t = bt - b * NT;
    int c  = threadIdx.x;
    __shared__ float txt[CTD];
    __shared__ float red[256];
    const float* trow = text + (size_t)bt * CTD;
    txt[c] = trow[c]; txt[c+256] = trow[c+256];
    __syncthreads();
    red[c] = fabsf(txt[c]) + fabsf(txt[c+256]);
    __syncthreads();
    for (int s = 128; s; s >>= 1) { if (c < s) red[c] += red[c+s]; __syncthreads(); }
    if (c == 0) g_pad[bt] = (red[0] <= 1e-6f);
    float kc = bk[c], vc = bv[c];
#pragma unroll 4
    for (int kk = 0; kk < CTD; kk++) {
        float tv = txt[kk];
        kc += tv * Wk[kk*CVD + c];
        vc += tv * Wv[kk*CVD + c];
    }
    float ss = kc * kc;
#pragma unroll
    for (int o = 16; o; o >>= 1) ss += __shfl_xor_sync(~0u, ss, o);
    kc /= fmaxf(sqrtf(ss), 1e-6f);
    int h = c >> 5, d = c & 31;
    g_kT[((b*NHH + h)*DH + d)*TPAD + t] = kc;
    g_v[(size_t)bt*CVD + c] = vc;
}

// ---------------- order-preserving float<->uint ----------------
__device__ __forceinline__ uint32_t ford(float f) {
    uint32_t u = __float_as_uint(f);
    return (u & 0x80000000u) ? ~u : (u | 0x80000000u);
}
__device__ __forceinline__ float finv(uint32_t m) {
    uint32_t u = (m & 0x80000000u) ? (m ^ 0x80000000u) : ~m;
    return __uint_as_float(u);
}

// ---------------- attention: redux-based top-5 ----------------
__global__ __launch_bounds__(256) void attn_kernel(const float* __restrict__ logit_scale) {
    int row = blockIdx.x;
    int b   = row >> 12;
    int tid = threadIdx.x;
    int h = tid >> 5, lane = tid & 31;
    __shared__ float qs[CVD];
    __shared__ int   spad[NT];
    qs[tid] = g_q[(size_t)row * CVD + tid];
    if (tid < NT) spad[tid] = g_pad[b*NT + tid];
    __syncthreads();

    float ls = logit_scale[0];
    float scale = expf(fminf(fmaxf(ls, -2.f), 2.f)) * 0.17677669529663687f;

    const float* kT = g_kT + ((size_t)(b*NHH + h) * DH) * TPAD;
    float a0 = 0.f, a1 = 0.f, a2 = 0.f;
#pragma unroll
    for (int d = 0; d < DH; d++) {
        float qd = qs[h*DH + d];
        const float* kr = kT + d*TPAD;
        a0 += qd * kr[lane];
        a1 += qd * kr[lane + 32];
        a2 += qd * kr[lane + 64];
    }

    float s0 = !spad[lane] ? a0 * scale : -INFINITY;
    float s1 = (lane + 32 < NT && !spad[lane + 32]) ? a1 * scale : -INFINITY;
    float s2 = (lane + 64 < NT && !spad[lane + 64]) ? a2 * scale : -INFINITY;

    uint32_t o0 = ford(s0), o1 = ford(s1), o2 = ford(s2);

    float topv[TOPM]; int topt[TOPM];
#pragma unroll
    for (int it = 0; it < TOPM; it++) {
        uint32_t loc = o0 > o1 ? o0 : o1;
        if (o2 > loc) loc = o2;
        uint32_t m = __reduce_max_sync(0xffffffffu, loc);
        topv[it] = finv(m);
        int t;
        unsigned b0 = __ballot_sync(0xffffffffu, o0 == m);
        if (b0) t = __ffs(b0) - 1;
        else {
            unsigned b1 = __ballot_sync(0xffffffffu, o1 == m);
            if (b1) t = 32 + __ffs(b1) - 1;
            else {
                unsigned b2 = __ballot_sync(0xffffffffu, o2 == m);
                t = 64 + __ffs(b2) - 1;
            }
        }
        topt[it] = t;
        if ((t & 31) == lane) {
            if (t < 32) o0 = 0u; else if (t < 64) o1 = 0u; else o2 = 0u;
        }
    }

    float outv = 0.f;
    float mx = topv[0];
    if (!(mx == -INFINITY)) {
        float e[TOPM]; float ws = 0.f;
#pragma unroll
        for (int i = 0; i < TOPM; i++) { e[i] = expf(topv[i] - mx); ws += e[i]; }
        float inv = 1.f / ws;
        const float* vb = g_v + (size_t)b * NT * CVD + h * DH + lane;
#pragma unroll
        for (int i = 0; i < TOPM; i++) outv += (e[i] * inv) * vb[(size_t)topt[i] * CVD];
    }
    size_t oi = (size_t)row * CVD + h*DH + lane;
    __nv_bfloat16 hh, ll; bf16_split(outv, hh, ll);
    g_ah[oi] = hh; g_al[oi] = ll;
}

// ---------------- mma helper ----------------
__device__ __forceinline__ void mma16(float* c, const uint32_t* a, const uint32_t* b) {
    asm volatile("mma.sync.aligned.m16n8k16.row.col.f32.bf16.bf16.f32 "
        "{%0,%1,%2,%3}, {%4,%5,%6,%7}, {%8,%9}, {%0,%1,%2,%3};"
        : "+f"(c[0]), "+f"(c[1]), "+f"(c[2]), "+f"(c[3])
        : "r"(a[0]), "r"(a[1]), "r"(a[2]), "r"(a[3]), "r"(b[0]), "r"(b[1]));
}

// ---------------- split-bf16 GEMM, BK=32, double-buffered dynamic smem ----------------
// C[M x N] = (Ah+Al)[M][K] @ Wpacked[K/2][N] (hi/lo). mode: 0 plain, 1 gelu->split, 2 l2norm, 3 +res.
// Block 128x64, 8 warps (4M x 2N), warp 32x32. 48 MMAs/warp per 32-k tile.
#define A_ELE (16*136)
#define B_ELE (16*72)
#define GEMM_SMEM ((4*A_ELE + 4*B_ELE)*4)

__global__ __launch_bounds__(256) void gemm_split_kernel(
    const __nv_bfloat16* __restrict__ Ahp, const __nv_bfloat16* __restrict__ Alp,
    const uint32_t* __restrict__ Bhp, const uint32_t* __restrict__ Blp,
    const float* __restrict__ bias, const float* __restrict__ res,
    float* __restrict__ outF, __nv_bfloat16* __restrict__ outH, __nv_bfloat16* __restrict__ outL,
    int K, int N, int mode)
{
    extern __shared__ uint32_t dsm[];
    uint32_t* AhS = dsm;                     // [2][16][136]
    uint32_t* AlS = dsm + 2*A_ELE;
    uint32_t* BhS = dsm + 4*A_ELE;           // [2][16][72]
    uint32_t* BlS = dsm + 4*A_ELE + 2*B_ELE;

    int tid  = threadIdx.x;
    int lane = tid & 31, wid = tid >> 5;
    int warpM = wid & 3, warpN = wid >> 2;
    int g = lane >> 2, t4 = lane & 3;
    int m0 = blockIdx.y * 128, n0 = blockIdx.x * 64;
    int mbase = warpM * 32, nbase = warpN * 32;

    float c[2][4][4];
#pragma unroll
    for (int i = 0; i < 2; i++)
#pragma unroll
        for (int j = 0; j < 4; j++)
#pragma unroll
            for (int l = 0; l < 4; l++) c[i][j][l] = 0.f;

    // loaders
    int ar = tid >> 1, ha = tid & 1;        // A: row ar, k-half ha (16 bf16 each)
    int bn = tid & 63, rw = tid >> 6;       // B: col bn, pair-row group rw (4 rows)
    const __nv_bfloat16* Aph = Ahp + (size_t)(m0 + ar) * K + 16*ha;
    const __nv_bfloat16* Apl = Alp + (size_t)(m0 + ar) * K + 16*ha;
    const uint32_t* Bph = Bhp + (size_t)(rw*4) * N + n0 + bn;
    const uint32_t* Bpl = Blp + (size_t)(rw*4) * N + n0 + bn;

    uint4 a0h, a1h, a0l, a1l;
    uint32_t rbh[4], rbl[4];

    auto load_regs = [&](int k0) {
        a0h = *(const uint4*)(Aph + k0);
        a1h = *(const uint4*)(Aph + k0 + 8);
        a0l = *(const uint4*)(Apl + k0);
        a1l = *(const uint4*)(Apl + k0 + 8);
        const uint32_t* bh = Bph + (size_t)(k0 >> 1) * N;
        const uint32_t* bl = Bpl + (size_t)(k0 >> 1) * N;
        rbh[0] = bh[0]; rbh[1] = bh[N]; rbh[2] = bh[2*N]; rbh[3] = bh[3*N];
        rbl[0] = bl[0]; rbl[1] = bl[N]; rbl[2] = bl[2*N]; rbl[3] = bl[3*N];
    };
    auto store_stage = [&](int st) {
        int k2a = 8*ha;
        int colA = ar ^ (ha << 4);          // xor-16 swizzle kills STS conflicts
        uint32_t* ah = AhS + st*A_ELE + k2a*136 + colA;
        uint32_t* al = AlS + st*A_ELE + k2a*136 + colA;
        ah[0*136] = a0h.x; ah[1*136] = a0h.y; ah[2*136] = a0h.z; ah[3*136] = a0h.w;
        ah[4*136] = a1h.x; ah[5*136] = a1h.y; ah[6*136] = a1h.z; ah[7*136] = a1h.w;
        al[0*136] = a0l.x; al[1*136] = a0l.y; al[2*136] = a0l.z; al[3*136] = a0l.w;
        al[4*136] = a1l.x; al[5*136] = a1l.y; al[6*136] = a1l.z; al[7*136] = a1l.w;
        uint32_t* bh = BhS + st*B_ELE + (rw*4)*72 + bn;
        uint32_t* bl = BlS + st*B_ELE + (rw*4)*72 + bn;
        bh[0] = rbh[0]; bh[72] = rbh[1]; bh[144] = rbh[2]; bh[216] = rbh[3];
        bl[0] = rbl[0]; bl[72] = rbl[1]; bl[144] = rbl[2]; bl[216] = rbl[3];
    };

    load_regs(0);
    store_stage(0);

    int stage = 0;
    for (int k0 = 0; k0 < K; k0 += 32) {
        __syncthreads();
        bool more = (k0 + 32) < K;
        if (more) load_regs(k0 + 32);

#pragma unroll
        for (int ks2 = 0; ks2 < 2; ks2++) {
            int colx = ks2 << 4;
            const uint32_t* aBh = AhS + stage*A_ELE + (8*ks2)*136;
            const uint32_t* aBl = AlS + stage*A_ELE + (8*ks2)*136;
            const uint32_t* bBh = BhS + stage*B_ELE + (8*ks2)*72;
            const uint32_t* bBl = BlS + stage*B_ELE + (8*ks2)*72;
            uint32_t ah[2][4], al[2][4], bh[4][2], blo[4][2];
#pragma unroll
            for (int mt = 0; mt < 2; mt++) {
                int rx  = (mbase + mt*16 + g) ^ colx;
                ah[mt][0] = aBh[(t4  )*136 + rx];   ah[mt][1] = aBh[(t4  )*136 + rx + 8];
                ah[mt][2] = aBh[(t4+4)*136 + rx];   ah[mt][3] = aBh[(t4+4)*136 + rx + 8];
                al[mt][0] = aBl[(t4  )*136 + rx];   al[mt][1] = aBl[(t4  )*136 + rx + 8];
                al[mt][2] = aBl[(t4+4)*136 + rx];   al[mt][3] = aBl[(t4+4)*136 + rx + 8];
            }
#pragma unroll
            for (int nt = 0; nt < 4; nt++) {
                int cn = nbase + nt*8 + g;
                bh[nt][0]  = bBh[(t4  )*72 + cn];   bh[nt][1]  = bBh[(t4+4)*72 + cn];
                blo[nt][0] = bBl[(t4  )*72 + cn];   blo[nt][1] = bBl[(t4+4)*72 + cn];
            }
#pragma unroll
            for (int mt = 0; mt < 2; mt++)
#pragma unroll
                for (int nt = 0; nt < 4; nt++) {
                    mma16(c[mt][nt], al[mt], bh[nt]);
                    mma16(c[mt][nt], ah[mt], blo[nt]);
                    mma16(c[mt][nt], ah[mt], bh[nt]);
                }
        }

        if (more) store_stage(stage ^ 1);
        stage ^= 1;
    }

    // epilogue
#pragma unroll
    for (int mt = 0; mt < 2; mt++)
#pragma unroll
        for (int nt = 0; nt < 4; nt++) {
            int col = n0 + nbase + nt*8 + t4*2;
            float b0v = bias[col], b1v = bias[col + 1];
            c[mt][nt][0] += b0v; c[mt][nt][1] += b1v;
            c[mt][nt][2] += b0v; c[mt][nt][3] += b1v;
        }

    if (mode == 2) {
#pragma unroll
        for (int mt = 0; mt < 2; mt++) {
            float ss0 = 0.f, ss1 = 0.f;
#pragma unroll
            for (int nt = 0; nt < 4; nt++) {
                ss0 += c[mt][nt][0]*c[mt][nt][0] + c[mt][nt][1]*c[mt][nt][1];
                ss1 += c[mt][nt][2]*c[mt][nt][2] + c[mt][nt][3]*c[mt][nt][3];
            }
            ss0 += __shfl_xor_sync(~0u, ss0, 1); ss0 += __shfl_xor_sync(~0u, ss0, 2);
            ss1 += __shfl_xor_sync(~0u, ss1, 1); ss1 += __shfl_xor_sync(~0u, ss1, 2);
            float i0 = 1.f / fmaxf(sqrtf(ss0), 1e-6f);
            float i1 = 1.f / fmaxf(sqrtf(ss1), 1e-6f);
#pragma unroll
            for (int nt = 0; nt < 4; nt++) {
                c[mt][nt][0] *= i0; c[mt][nt][1] *= i0;
                c[mt][nt][2] *= i1; c[mt][nt][3] *= i1;
            }
        }
    }

#pragma unroll
    for (int mt = 0; mt < 2; mt++)
#pragma unroll
        for (int nt = 0; nt < 4; nt++) {
            int col = n0 + nbase + nt*8 + t4*2;
            size_t r0 = (size_t)(m0 + mbase + mt*16 + g);
            size_t r1 = r0 + 8;
            float v0 = c[mt][nt][0], v1 = c[mt][nt][1];
            float v2 = c[mt][nt][2], v3 = c[mt][nt][3];
            if (mode == 1) {
                v0 = 0.5f*v0*(1.f + erff(v0*0.70710678118654752f));
                v1 = 0.5f*v1*(1.f + erff(v1*0.70710678118654752f));
                v2 = 0.5f*v2*(1.f + erff(v2*0.70710678118654752f));
                v3 = 0.5f*v3*(1.f + erff(v3*0.70710678118654752f));
                __nv_bfloat16 h0,l0,h1,l1,h2,l2,h3,l3;
                bf16_split(v0,h0,l0); bf16_split(v1,h1,l1);
                bf16_split(v2,h2,l2); bf16_split(v3,h3,l3);
                __nv_bfloat162 hp0 = __halves2bfloat162(h0,h1), hp1 = __halves2bfloat162(h2,h3);
                __nv_bfloat162 lp0 = __halves2bfloat162(l0,l1), lp1 = __halves2bfloat162(l2,l3);
                *(uint32_t*)&outH[r0*N + col] = *(uint32_t*)&hp0;
                *(uint32_t*)&outL[r0*N + col] = *(uint32_t*)&lp0;
                *(uint32_t*)&outH[r1*N + col] = *(uint32_t*)&hp1;
                *(uint32_t*)&outL[r1*N + col] = *(uint32_t*)&lp1;
            } else {
                if (mode == 3) {
                    v0 += res[r0*N + col]; v1 += res[r0*N + col + 1];
                    v2 += res[r1*N + col]; v3 += res[r1*N + col + 1];
                }
                *(float2*)&outF[r0*N + col] = make_float2(v0, v1);
                *(float2*)&outF[r1*N + col] = make_float2(v2, v3);
            }
        }
}

// ---------------- launch ----------------
extern "C" void kernel_launch(void* const* d_in, const int* in_sizes, int n_in,
                              void* d_out, int out_size) {
    const float* vis   = (const float*)d_in[0];
    const float* text  = (const float*)d_in[1];
    const float* Wq    = (const float*)d_in[2];
    const float* bq    = (const float*)d_in[3];
    const float* Wk    = (const float*)d_in[4];
    const float* bk    = (const float*)d_in[5];
    const float* Wv    = (const float*)d_in[6];
    const float* bv    = (const float*)d_in[7];
    const float* Wo    = (const float*)d_in[8];
    const float* bo    = (const float*)d_in[9];
    const float* g1    = (const float*)d_in[10];
    const float* b1    = (const float*)d_in[11];
    const float* g2    = (const float*)d_in[12];
    const float* b2    = (const float*)d_in[13];
    const float* Wf1   = (const float*)d_in[14];
    const float* bf1   = (const float*)d_in[15];
    const float* Wf2   = (const float*)d_in[16];
    const float* bf2   = (const float*)d_in[17];
    const float* ls    = (const float*)d_in[18];
    const float* alpha = (const float*)d_in[19];
    float* out = (float*)d_out;

    __nv_bfloat16 *pxh, *pxl, *pah, *pal, *py2h, *py2l, *phh, *phl;
    uint32_t *pwqh, *pwql, *pwoh, *pwol, *pw1h, *pw1l, *pw2h, *pw2l;
    float *pq, *pproj, *py2;
    cudaGetSymbolAddress((void**)&pxh,  g_xh);  cudaGetSymbolAddress((void**)&pxl,  g_xl);
    cudaGetSymbolAddress((void**)&pah,  g_ah);  cudaGetSymbolAddress((void**)&pal,  g_al);
    cudaGetSymbolAddress((void**)&py2h, g_y2h); cudaGetSymbolAddress((void**)&py2l, g_y2l);
    cudaGetSymbolAddress((void**)&phh,  g_hh);  cudaGetSymbolAddress((void**)&phl,  g_hl);
    cudaGetSymbolAddress((void**)&pwqh, g_wqh); cudaGetSymbolAddress((void**)&pwql, g_wql);
    cudaGetSymbolAddress((void**)&pwoh, g_woh); cudaGetSymbolAddress((void**)&pwol, g_wol);
    cudaGetSymbolAddress((void**)&pw1h, g_w1h); cudaGetSymbolAddress((void**)&pw1l, g_w1l);
    cudaGetSymbolAddress((void**)&pw2h, g_w2h); cudaGetSymbolAddress((void**)&pw2l, g_w2l);
    cudaGetSymbolAddress((void**)&pq,   g_q);
    cudaGetSymbolAddress((void**)&pproj,g_proj);
    cudaGetSymbolAddress((void**)&py2,  g_y2);

    cudaFuncSetAttribute(gemm_split_kernel,
                         cudaFuncAttributeMaxDynamicSharedMemorySize, GEMM_SMEM);

    wsplit_kernel<<<(CVD/2)*CVD/256, 256>>>(Wq,  pwqh, pwql, CVD);
    wsplit_kernel<<<(CVD/2)*CVD/256, 256>>>(Wo,  pwoh, pwol, CVD);
    wsplit_kernel<<<(CVD/2)*FFN/256, 256>>>(Wf1, pw1h, pw1l, FFN);
    wsplit_kernel<<<(FFN/2)*CVD/256, 256>>>(Wf2, pw2h, pw2l, CVD);

    ln1_kernel<<<ROWS/8, 256>>>(vis, g1, b1);
    kv_kernel<<<NB*NT, 256>>>(text, Wk, bk, Wv, bv);

    gemm_split_kernel<<<dim3(CVD/64, ROWS/128), 256, GEMM_SMEM>>>(
        pxh, pxl, pwqh, pwql, bq, nullptr, pq, nullptr, nullptr, CVD, CVD, 2);
    attn_kernel<<<ROWS, 256>>>(ls);
    gemm_split_kernel<<<dim3(CVD/64, ROWS/128), 256, GEMM_SMEM>>>(
        pah, pal, pwoh, pwol, bo, nullptr, pproj, nullptr, nullptr, CVD, CVD, 0);
    ln2res_kernel<<<ROWS/8, 256>>>(g2, b2, alpha);
    gemm_split_kernel<<<dim3(FFN/64, ROWS/128), 256, GEMM_SMEM>>>(
        py2h, py2l, pw1h, pw1l, bf1, nullptr, nullptr, phh, phl, CVD, FFN, 1);
    gemm_split_kernel<<<dim3(CVD/64, ROWS/128), 256, GEMM_SMEM>>>(
        phh, phl, pw2h, pw2l, bf2, py2, out, nullptr, nullptr, FFN, CVD, 3);
}

// round 10
// speedup vs baseline: 1.5226x; 1.0690x over previous
#include <cuda_runtime.h>
#include <cuda_bf16.h>
#include <math.h>
#include <stdint.h>

// ---------------- problem constants ----------------
#define NB   8
#define NN   4096          // H*W
#define CVD  256
#define CTD  512
#define NT   77
#define TPAD 96
#define NHH  8
#define DH   32
#define TOPM 5
#define ROWS (NB*NN)       // 32768

// ---------------- scratch (device globals; no allocs allowed) ----------------
__device__ float g_x[ROWS*CVD];          // LN1 output
__device__ float g_q[ROWS*CVD];          // q projection (l2-normed in epilogue)
__device__ float g_kT[NB*NHH*DH*TPAD];   // k transposed [b][h][d][t], l2-normed; t>=77 stays 0
__device__ float g_v[NB*NT*CVD];         // v
__device__ int   g_pad[NB*NT];           // pad flags
__device__ float g_aligned[ROWS*CVD];    // attention output
__device__ float g_proj[ROWS*CVD];       // aligned @ Wo + bo
__device__ float g_y2[ROWS*CVD];         // LN2 output
__device__ float g_hdn[ROWS*4*CVD];      // FFN hidden (gelu)

// ---------------- LN1 ----------------
__global__ __launch_bounds__(256) void ln1_kernel(const float* __restrict__ in,
                                                  const float* __restrict__ g,
                                                  const float* __restrict__ b) {
    int warp = (blockIdx.x * blockDim.x + threadIdx.x) >> 5;
    int lane = threadIdx.x & 31;
    const float* row = in + (size_t)warp * CVD;
    float v[8]; float s = 0.f, ss = 0.f;
#pragma unroll
    for (int i = 0; i < 8; i++) { v[i] = row[lane*8 + i]; s += v[i]; ss += v[i]*v[i]; }
#pragma unroll
    for (int o = 16; o; o >>= 1) { s += __shfl_xor_sync(~0u, s, o); ss += __shfl_xor_sync(~0u, ss, o); }
    float mu  = s * (1.f/CVD);
    float var = ss * (1.f/CVD) - mu*mu;
    float inv = rsqrtf(var + 1e-5f);
    float* orow = g_x + (size_t)warp * CVD;
#pragma unroll
    for (int i = 0; i < 8; i++) { int c = lane*8 + i; orow[c] = (v[i]-mu)*inv*g[c] + b[c]; }
}

// ---------------- LN2 + residual ----------------
__global__ __launch_bounds__(256) void ln2res_kernel(const float* __restrict__ g,
                                                     const float* __restrict__ b,
                                                     const float* __restrict__ alpha_p) {
    int warp = (blockIdx.x * blockDim.x + threadIdx.x) >> 5;
    int lane = threadIdx.x & 31;
    float alpha = alpha_p[0];
    const float* xr = g_x    + (size_t)warp * CVD;
    const float* pr = g_proj + (size_t)warp * CVD;
    float v[8]; float s = 0.f, ss = 0.f;
#pragma unroll
    for (int i = 0; i < 8; i++) {
        int c = lane*8 + i;
        v[i] = xr[c] + alpha * pr[c];
        s += v[i]; ss += v[i]*v[i];
    }
#pragma unroll
    for (int o = 16; o; o >>= 1) { s += __shfl_xor_sync(~0u, s, o); ss += __shfl_xor_sync(~0u, ss, o); }
    float mu  = s * (1.f/CVD);
    float var = ss * (1.f/CVD) - mu*mu;
    float inv = rsqrtf(var + 1e-5f);
    float* orow = g_y2 + (size_t)warp * CVD;
#pragma unroll
    for (int i = 0; i < 8; i++) { int c = lane*8 + i; orow[c] = (v[i]-mu)*inv*g[c] + b[c]; }
}

// ---------------- K/V projection + pad flags + k l2norm + K transpose ----------------
__global__ __launch_bounds__(256) void kv_kernel(const float* __restrict__ text,
                                                 const float* __restrict__ Wk, const float* __restrict__ bk,
                                                 const float* __restrict__ Wv, const float* __restrict__ bv) {
    int bt = blockIdx.x;          // b*NT + t
    int b  = bt / NT, t = bt - b * NT;
    int c  = threadIdx.x;         // output channel
    __shared__ float txt[CTD];
    __shared__ float red[256];
    const float* trow = text + (size_t)bt * CTD;
    txt[c] = trow[c]; txt[c+256] = trow[c+256];
    __syncthreads();
    red[c] = fabsf(txt[c]) + fabsf(txt[c+256]);
    __syncthreads();
    for (int s = 128; s; s >>= 1) { if (c < s) red[c] += red[c+s]; __syncthreads(); }
    if (c == 0) g_pad[bt] = (red[0] <= 1e-6f);
    float kc = bk[c], vc = bv[c];
#pragma unroll 4
    for (int kk = 0; kk < CTD; kk++) {
        float tv = txt[kk];
        kc += tv * Wk[kk*CVD + c];
        vc += tv * Wv[kk*CVD + c];
    }
    float ss = kc * kc;
#pragma unroll
    for (int o = 16; o; o >>= 1) ss += __shfl_xor_sync(~0u, ss, o);
    kc /= fmaxf(sqrtf(ss), 1e-6f);
    int h = c >> 5, d = c & 31;
    g_kT[((b*NHH + h)*DH + d)*TPAD + t] = kc;       // transposed store
    g_v[(size_t)bt*CVD + c] = vc;
}

// ---------------- order-preserving float<->uint ----------------
__device__ __forceinline__ uint32_t ford(float f) {
    uint32_t u = __float_as_uint(f);
    return (u & 0x80000000u) ? ~u : (u | 0x80000000u);
}
__device__ __forceinline__ float finv(uint32_t m) {
    uint32_t u = (m & 0x80000000u) ? (m ^ 0x80000000u) : ~m;
    return __uint_as_float(u);
}

// ---------------- attention: block per (b,n), warp per head; redux-based top-5 ----------------
__global__ __launch_bounds__(256) void attn_kernel(const float* __restrict__ logit_scale) {
    int row = blockIdx.x;
    int b   = row >> 12;
    int tid = threadIdx.x;
    int h = tid >> 5, lane = tid & 31;
    __shared__ float qs[CVD];
    __shared__ int   spad[NT];
    qs[tid] = g_q[(size_t)row * CVD + tid];
    if (tid < NT) spad[tid] = g_pad[b*NT + tid];
    __syncthreads();

    float ls = logit_scale[0];
    float scale = expf(fminf(fmaxf(ls, -2.f), 2.f)) * 0.17677669529663687f;

    const float* kT = g_kT + ((size_t)(b*NHH + h) * DH) * TPAD;  // [d][t]
    float a0 = 0.f, a1 = 0.f, a2 = 0.f;
#pragma unroll
    for (int d = 0; d < DH; d++) {
        float qd = qs[h*DH + d];
        const float* kr = kT + d*TPAD;
        a0 += qd * kr[lane];
        a1 += qd * kr[lane + 32];
        a2 += qd * kr[lane + 64];
    }

    float s0 = !spad[lane] ? a0 * scale : -INFINITY;
    float s1 = (lane + 32 < NT && !spad[lane + 32]) ? a1 * scale : -INFINITY;
    float s2 = (lane + 64 < NT && !spad[lane + 64]) ? a2 * scale : -INFINITY;

    uint32_t o0 = ford(s0), o1 = ford(s1), o2 = ford(s2);

    float topv[TOPM]; int topt[TOPM];
#pragma unroll
    for (int it = 0; it < TOPM; it++) {
        uint32_t loc = o0 > o1 ? o0 : o1;
        if (o2 > loc) loc = o2;
        uint32_t m = __reduce_max_sync(0xffffffffu, loc);
        topv[it] = finv(m);
        int t;
        unsigned b0 = __ballot_sync(0xffffffffu, o0 == m);
        if (b0) t = __ffs(b0) - 1;
        else {
            unsigned b1 = __ballot_sync(0xffffffffu, o1 == m);
            if (b1) t = 32 + __ffs(b1) - 1;
            else {
                unsigned b2 = __ballot_sync(0xffffffffu, o2 == m);
                t = 64 + __ffs(b2) - 1;
            }
        }
        topt[it] = t;
        if ((t & 31) == lane) {
            if (t < 32) o0 = 0u; else if (t < 64) o1 = 0u; else o2 = 0u;
        }
    }

    float outv = 0.f;
    float mx = topv[0];
    if (!(mx == -INFINITY)) {
        float e[TOPM]; float ws = 0.f;
#pragma unroll
        for (int i = 0; i < TOPM; i++) { e[i] = expf(topv[i] - mx); ws += e[i]; }
        float inv = 1.f / ws;
        const float* vb = g_v + (size_t)b * NT * CVD + h * DH + lane;
#pragma unroll
        for (int i = 0; i < TOPM; i++) outv += (e[i] * inv) * vb[(size_t)topt[i] * CVD];
    }
    g_aligned[(size_t)row * CVD + h*DH + lane] = outv;
}

// ---------------- bf16 split helpers ----------------
__device__ __forceinline__ void bf16_split_pack(float x0, float x1, uint32_t& hi, uint32_t& lo) {
    __nv_bfloat16 h0 = __float2bfloat16_rn(x0);
    __nv_bfloat16 h1 = __float2bfloat16_rn(x1);
    __nv_bfloat16 l0 = __float2bfloat16_rn(x0 - __bfloat162float(h0));
    __nv_bfloat16 l1 = __float2bfloat16_rn(x1 - __bfloat162float(h1));
    hi = (uint32_t)__bfloat16_as_ushort(h0) | ((uint32_t)__bfloat16_as_ushort(h1) << 16);
    lo = (uint32_t)__bfloat16_as_ushort(l0) | ((uint32_t)__bfloat16_as_ushort(l1) << 16);
}
__device__ __forceinline__ void mma16(float* c, const uint32_t* a, const uint32_t* b) {
    asm volatile("mma.sync.aligned.m16n8k16.row.col.f32.bf16.bf16.f32 "
        "{%0,%1,%2,%3}, {%4,%5,%6,%7}, {%8,%9}, {%0,%1,%2,%3};"
        : "+f"(c[0]), "+f"(c[1]), "+f"(c[2]), "+f"(c[3])
        : "r"(a[0]), "r"(a[1]), "r"(a[2]), "r"(a[3]), "r"(b[0]), "r"(b[1]));
}

// ---------------- split-bf16 tensor-core GEMM (3x m16n8k16): C = A@B + bias ----------------
// mode: 0 plain, 1 exact gelu, 2 per-32-col l2norm. res: optional +residual.
// Block 128x64, BK=16, 8 warps (4M x 2N), warp 32x32 = 2x4 tiles. 2-stage smem double buffer.
__global__ __launch_bounds__(256) void gemm_bf16s_kernel(const float* __restrict__ A,
                                                         const float* __restrict__ B,
                                                         const float* __restrict__ bias,
                                                         const float* __restrict__ res,
                                                         float* __restrict__ C,
                                                         int M, int N, int K, int mode) {
    __shared__ uint32_t Ah[2][8][136], Al[2][8][136];  // stride 136 = 8 mod 32 -> conflict-free
    __shared__ uint32_t Bh[2][8][72],  Bl[2][8][72];

    int tid  = threadIdx.x;
    int lane = tid & 31, wid = tid >> 5;
    int warpM = wid & 3, warpN = wid >> 2;
    int g = lane >> 2, t4 = lane & 3;
    int m0 = blockIdx.y * 128, n0 = blockIdx.x * 64;
    int mbase = warpM * 32, nbase = warpN * 32;

    float c[2][4][4];
#pragma unroll
    for (int i = 0; i < 2; i++)
#pragma unroll
        for (int j = 0; j < 4; j++)
#pragma unroll
            for (int l = 0; l < 4; l++) c[i][j][l] = 0.f;

    // A loader: 128 rows x 16 k / 256 thr -> 8 floats each (2x float4)
    int ar   = tid >> 1;
    int ha   = tid & 1;
    int k2a  = 4*ha;
    // B loader: col bn, pair rows k2b, k2b+1
    int bn   = tid & 63;
    int k2b  = (tid >> 6) * 2;
    const float* Aptr = A + (size_t)(m0 + ar) * K + 8*ha;
    const float* Bptr = B + (size_t)(2*k2b) * N + n0 + bn;

    float4 av0, av1;
    float  b00, b01, b10, b11;
    av0 = *(const float4*)(Aptr);
    av1 = *(const float4*)(Aptr + 4);
    b00 = Bptr[0]; b01 = Bptr[N]; b10 = Bptr[2*N]; b11 = Bptr[3*N];

    // stage tile 0
    {
        uint32_t h, l;
        bf16_split_pack(av0.x, av0.y, h, l); Ah[0][k2a+0][ar] = h; Al[0][k2a+0][ar] = l;
        bf16_split_pack(av0.z, av0.w, h, l); Ah[0][k2a+1][ar] = h; Al[0][k2a+1][ar] = l;
        bf16_split_pack(av1.x, av1.y, h, l); Ah[0][k2a+2][ar] = h; Al[0][k2a+2][ar] = l;
        bf16_split_pack(av1.z, av1.w, h, l); Ah[0][k2a+3][ar] = h; Al[0][k2a+3][ar] = l;
        bf16_split_pack(b00, b01, h, l);     Bh[0][k2b  ][bn] = h; Bl[0][k2b  ][bn] = l;
        bf16_split_pack(b10, b11, h, l);     Bh[0][k2b+1][bn] = h; Bl[0][k2b+1][bn] = l;
    }

    int stage = 0;
    for (int k0 = 0; k0 < K; k0 += 16) {
        __syncthreads();
        bool more = (k0 + 16) < K;
        if (more) {
            av0 = *(const float4*)(Aptr + k0 + 16);
            av1 = *(const float4*)(Aptr + k0 + 20);
            const float* bp = Bptr + (size_t)(k0 + 16) * N;
            b00 = bp[0]; b01 = bp[N]; b10 = bp[2*N]; b11 = bp[3*N];
        }

        uint32_t ah[2][4], al[2][4], bh[4][2], blo[4][2];
#pragma unroll
        for (int mt = 0; mt < 2; mt++) {
            int r0 = mbase + mt*16 + g;
            ah[mt][0] = Ah[stage][t4  ][r0];   ah[mt][1] = Ah[stage][t4  ][r0+8];
            ah[mt][2] = Ah[stage][t4+4][r0];   ah[mt][3] = Ah[stage][t4+4][r0+8];
            al[mt][0] = Al[stage][t4  ][r0];   al[mt][1] = Al[stage][t4  ][r0+8];
            al[mt][2] = Al[stage][t4+4][r0];   al[mt][3] = Al[stage][t4+4][r0+8];
        }
#pragma unroll
        for (int nt = 0; nt < 4; nt++) {
            int cn = nbase + nt*8 + g;
            bh[nt][0]  = Bh[stage][t4][cn];    bh[nt][1]  = Bh[stage][t4+4][cn];
            blo[nt][0] = Bl[stage][t4][cn];    blo[nt][1] = Bl[stage][t4+4][cn];
        }
#pragma unroll
        for (int mt = 0; mt < 2; mt++)
#pragma unroll
            for (int nt = 0; nt < 4; nt++) {
                mma16(c[mt][nt], al[mt], bh[nt]);
                mma16(c[mt][nt], ah[mt], blo[nt]);
                mma16(c[mt][nt], ah[mt], bh[nt]);
            }

        if (more) {
            int ns = stage ^ 1;
            uint32_t h, l;
            bf16_split_pack(av0.x, av0.y, h, l); Ah[ns][k2a+0][ar] = h; Al[ns][k2a+0][ar] = l;
            bf16_split_pack(av0.z, av0.w, h, l); Ah[ns][k2a+1][ar] = h; Al[ns][k2a+1][ar] = l;
            bf16_split_pack(av1.x, av1.y, h, l); Ah[ns][k2a+2][ar] = h; Al[ns][k2a+2][ar] = l;
            bf16_split_pack(av1.z, av1.w, h, l); Ah[ns][k2a+3][ar] = h; Al[ns][k2a+3][ar] = l;
            bf16_split_pack(b00, b01, h, l);     Bh[ns][k2b  ][bn] = h; Bl[ns][k2b  ][bn] = l;
            bf16_split_pack(b10, b11, h, l);     Bh[ns][k2b+1][bn] = h; Bl[ns][k2b+1][bn] = l;
        }
        stage ^= 1;
    }

    // epilogue: bias -> (optional l2norm) -> (optional gelu) -> (optional res) -> store
#pragma unroll
    for (int mt = 0; mt < 2; mt++)
#pragma unroll
        for (int nt = 0; nt < 4; nt++) {
            int col = n0 + nbase + nt*8 + t4*2;
            float b0v = bias[col], b1v = bias[col + 1];
            c[mt][nt][0] += b0v; c[mt][nt][1] += b1v;
            c[mt][nt][2] += b0v; c[mt][nt][3] += b1v;
        }

    if (mode == 2) {
#pragma unroll
        for (int mt = 0; mt < 2; mt++) {
            float ss0 = 0.f, ss1 = 0.f;
#pragma unroll
            for (int nt = 0; nt < 4; nt++) {
                ss0 += c[mt][nt][0]*c[mt][nt][0] + c[mt][nt][1]*c[mt][nt][1];
                ss1 += c[mt][nt][2]*c[mt][nt][2] + c[mt][nt][3]*c[mt][nt][3];
            }
            ss0 += __shfl_xor_sync(~0u, ss0, 1); ss0 += __shfl_xor_sync(~0u, ss0, 2);
            ss1 += __shfl_xor_sync(~0u, ss1, 1); ss1 += __shfl_xor_sync(~0u, ss1, 2);
            float i0 = 1.f / fmaxf(sqrtf(ss0), 1e-6f);
            float i1 = 1.f / fmaxf(sqrtf(ss1), 1e-6f);
#pragma unroll
            for (int nt = 0; nt < 4; nt++) {
                c[mt][nt][0] *= i0; c[mt][nt][1] *= i0;
                c[mt][nt][2] *= i1; c[mt][nt][3] *= i1;
            }
        }
    }

#pragma unroll
    for (int mt = 0; mt < 2; mt++)
#pragma unroll
        for (int nt = 0; nt < 4; nt++) {
            int col = n0 + nbase + nt*8 + t4*2;
            size_t r0 = (size_t)(m0 + mbase + mt*16 + g);
            size_t r1 = r0 + 8;
            float v0 = c[mt][nt][0], v1 = c[mt][nt][1];
            float v2 = c[mt][nt][2], v3 = c[mt][nt][3];
            if (mode == 1) {
                v0 = 0.5f*v0*(1.f + erff(v0*0.70710678118654752f));
                v1 = 0.5f*v1*(1.f + erff(v1*0.70710678118654752f));
                v2 = 0.5f*v2*(1.f + erff(v2*0.70710678118654752f));
                v3 = 0.5f*v3*(1.f + erff(v3*0.70710678118654752f));
            }
            if (res) {
                v0 += res[r0*N + col]; v1 += res[r0*N + col + 1];
                v2 += res[r1*N + col]; v3 += res[r1*N + col + 1];
            }
            *(float2*)&C[r0*N + col] = make_float2(v0, v1);
            *(float2*)&C[r1*N + col] = make_float2(v2, v3);
        }
}

// ---------------- launch ----------------
extern "C" void kernel_launch(void* const* d_in, const int* in_sizes, int n_in,
                              void* d_out, int out_size) {
    const float* vis   = (const float*)d_in[0];
    const float* text  = (const float*)d_in[1];
    const float* Wq    = (const float*)d_in[2];
    const float* bq    = (const float*)d_in[3];
    const float* Wk    = (const float*)d_in[4];
    const float* bk    = (const float*)d_in[5];
    const float* Wv    = (const float*)d_in[6];
    const float* bv    = (const float*)d_in[7];
    const float* Wo    = (const float*)d_in[8];
    const float* bo    = (const float*)d_in[9];
    const float* g1    = (const float*)d_in[10];
    const float* b1    = (const float*)d_in[11];
    const float* g2    = (const float*)d_in[12];
    const float* b2    = (const float*)d_in[13];
    const float* Wf1   = (const float*)d_in[14];
    const float* bf1   = (const float*)d_in[15];
    const float* Wf2   = (const float*)d_in[16];
    const float* bf2   = (const float*)d_in[17];
    const float* ls    = (const float*)d_in[18];
    const float* alpha = (const float*)d_in[19];
    float* out = (float*)d_out;

    float *px, *pq, *paligned, *pproj, *py2, *phdn;
    cudaGetSymbolAddress((void**)&px,       g_x);
    cudaGetSymbolAddress((void**)&pq,       g_q);
    cudaGetSymbolAddress((void**)&paligned, g_aligned);
    cudaGetSymbolAddress((void**)&pproj,    g_proj);
    cudaGetSymbolAddress((void**)&py2,      g_y2);
    cudaGetSymbolAddress((void**)&phdn,     g_hdn);

    ln1_kernel<<<ROWS/8, 256>>>(vis, g1, b1);
    kv_kernel<<<NB*NT, 256>>>(text, Wk, bk, Wv, bv);
    gemm_bf16s_kernel<<<dim3(CVD/64, ROWS/128), 256>>>(px, Wq, bq, nullptr, pq, ROWS, CVD, CVD, 2);
    attn_kernel<<<ROWS, 256>>>(ls);
    gemm_bf16s_kernel<<<dim3(CVD/64, ROWS/128), 256>>>(paligned, Wo, bo, nullptr, pproj, ROWS, CVD, CVD, 0);
    ln2res_kernel<<<ROWS/8, 256>>>(g2, b2, alpha);
    gemm_bf16s_kernel<<<dim3(4*CVD/64, ROWS/128), 256>>>(py2, Wf1, bf1, nullptr, phdn, ROWS, 4*CVD, CVD, 1);
    gemm_bf16s_kernel<<<dim3(CVD/64, ROWS/128), 256>>>(phdn, Wf2, bf2, py2, out, ROWS, CVD, 4*CVD, 0);
}

// round 11
// speedup vs baseline: 1.5749x; 1.0343x over previous
#include <cuda_runtime.h>
#include <cuda_bf16.h>
#include <math.h>
#include <stdint.h>

// ---------------- problem constants ----------------
#define NB   8
#define NN   4096          // H*W
#define CVD  256
#define CTD  512
#define NT   77
#define TPAD 96
#define NHH  8
#define DH   32
#define TOPM 5
#define ROWS (NB*NN)       // 32768

// ---------------- scratch (device globals; no allocs allowed) ----------------
__device__ float g_x[ROWS*CVD];          // LN1 output
__device__ float g_q[ROWS*CVD];          // q projection (l2-normed in epilogue)
__device__ float g_kT[NB*NHH*DH*TPAD];   // k transposed [b][h][d][t]
__device__ float g_v[NB*NT*CVD];         // v
__device__ int   g_pad[NB*NT];           // pad flags
__device__ float g_aligned[ROWS*CVD];    // attention output
__device__ float g_proj[ROWS*CVD];       // aligned @ Wo + bo
__device__ float g_y2[ROWS*CVD];         // LN2 output
__device__ float g_hdn[ROWS*4*CVD];      // FFN hidden (gelu)

// ---------------- LN1 ----------------
__global__ __launch_bounds__(256) void ln1_kernel(const float* __restrict__ in,
                                                  const float* __restrict__ g,
                                                  const float* __restrict__ b) {
    int warp = (blockIdx.x * blockDim.x + threadIdx.x) >> 5;
    int lane = threadIdx.x & 31;
    const float* row = in + (size_t)warp * CVD;
    float v[8]; float s = 0.f, ss = 0.f;
#pragma unroll
    for (int i = 0; i < 8; i++) { v[i] = row[lane*8 + i]; s += v[i]; ss += v[i]*v[i]; }
#pragma unroll
    for (int o = 16; o; o >>= 1) { s += __shfl_xor_sync(~0u, s, o); ss += __shfl_xor_sync(~0u, ss, o); }
    float mu  = s * (1.f/CVD);
    float var = ss * (1.f/CVD) - mu*mu;
    float inv = rsqrtf(var + 1e-5f);
    float* orow = g_x + (size_t)warp * CVD;
#pragma unroll
    for (int i = 0; i < 8; i++) { int c = lane*8 + i; orow[c] = (v[i]-mu)*inv*g[c] + b[c]; }
}

// ---------------- LN2 + residual ----------------
__global__ __launch_bounds__(256) void ln2res_kernel(const float* __restrict__ g,
                                                     const float* __restrict__ b,
                                                     const float* __restrict__ alpha_p) {
    int warp = (blockIdx.x * blockDim.x + threadIdx.x) >> 5;
    int lane = threadIdx.x & 31;
    float alpha = alpha_p[0];
    const float* xr = g_x    + (size_t)warp * CVD;
    const float* pr = g_proj + (size_t)warp * CVD;
    float v[8]; float s = 0.f, ss = 0.f;
#pragma unroll
    for (int i = 0; i < 8; i++) {
        int c = lane*8 + i;
        v[i] = xr[c] + alpha * pr[c];
        s += v[i]; ss += v[i]*v[i];
    }
#pragma unroll
    for (int o = 16; o; o >>= 1) { s += __shfl_xor_sync(~0u, s, o); ss += __shfl_xor_sync(~0u, ss, o); }
    float mu  = s * (1.f/CVD);
    float var = ss * (1.f/CVD) - mu*mu;
    float inv = rsqrtf(var + 1e-5f);
    float* orow = g_y2 + (size_t)warp * CVD;
#pragma unroll
    for (int i = 0; i < 8; i++) { int c = lane*8 + i; orow[c] = (v[i]-mu)*inv*g[c] + b[c]; }
}

// ---------------- K/V projection + pad flags + k l2norm + K transpose ----------------
__global__ __launch_bounds__(256) void kv_kernel(const float* __restrict__ text,
                                                 const float* __restrict__ Wk, const float* __restrict__ bk,
                                                 const float* __restrict__ Wv, const float* __restrict__ bv) {
    int bt = blockIdx.x;          // b*NT + t
    int b  = bt / NT, t = bt - b * NT;
    int c  = threadIdx.x;
    __shared__ float txt[CTD];
    __shared__ float red[256];
    const float* trow = text + (size_t)bt * CTD;
    txt[c] = trow[c]; txt[c+256] = trow[c+256];
    __syncthreads();
    red[c] = fabsf(txt[c]) + fabsf(txt[c+256]);
    __syncthreads();
    for (int s = 128; s; s >>= 1) { if (c < s) red[c] += red[c+s]; __syncthreads(); }
    if (c == 0) g_pad[bt] = (red[0] <= 1e-6f);
    float kc = bk[c], vc = bv[c];
#pragma unroll 4
    for (int kk = 0; kk < CTD; kk++) {
        float tv = txt[kk];
        kc += tv * Wk[kk*CVD + c];
        vc += tv * Wv[kk*CVD + c];
    }
    float ss = kc * kc;
#pragma unroll
    for (int o = 16; o; o >>= 1) ss += __shfl_xor_sync(~0u, ss, o);
    kc /= fmaxf(sqrtf(ss), 1e-6f);
    int h = c >> 5, d = c & 31;
    g_kT[((b*NHH + h)*DH + d)*TPAD + t] = kc;
    g_v[(size_t)bt*CVD + c] = vc;
}

// ---------------- order-preserving float<->uint ----------------
__device__ __forceinline__ uint32_t ford(float f) {
    uint32_t u = __float_as_uint(f);
    return (u & 0x80000000u) ? ~u : (u | 0x80000000u);
}
__device__ __forceinline__ float finv(uint32_t m) {
    uint32_t u = (m & 0x80000000u) ? (m ^ 0x80000000u) : ~m;
    return __uint_as_float(u);
}

// ---------------- attention: block per (b,n), warp per head; redux-based top-5 ----------------
__global__ __launch_bounds__(256) void attn_kernel(const float* __restrict__ logit_scale) {
    int row = blockIdx.x;
    int b   = row >> 12;
    int tid = threadIdx.x;
    int h = tid >> 5, lane = tid & 31;
    __shared__ float qs[CVD];
    __shared__ int   spad[NT];
    qs[tid] = g_q[(size_t)row * CVD + tid];
    if (tid < NT) spad[tid] = g_pad[b*NT + tid];
    __syncthreads();

    float ls = logit_scale[0];
    float scale = expf(fminf(fmaxf(ls, -2.f), 2.f)) * 0.17677669529663687f;

    const float* kT = g_kT + ((size_t)(b*NHH + h) * DH) * TPAD;  // [d][t]
    float a0 = 0.f, a1 = 0.f, a2 = 0.f;
#pragma unroll
    for (int d = 0; d < DH; d++) {
        float qd = qs[h*DH + d];
        const float* kr = kT + d*TPAD;
        a0 += qd * kr[lane];
        a1 += qd * kr[lane + 32];
        a2 += qd * kr[lane + 64];
    }

    float s0 = !spad[lane] ? a0 * scale : -INFINITY;
    float s1 = (lane + 32 < NT && !spad[lane + 32]) ? a1 * scale : -INFINITY;
    float s2 = (lane + 64 < NT && !spad[lane + 64]) ? a2 * scale : -INFINITY;

    uint32_t o0 = ford(s0), o1 = ford(s1), o2 = ford(s2);

    float topv[TOPM]; int topt[TOPM];
#pragma unroll
    for (int it = 0; it < TOPM; it++) {
        uint32_t loc = o0 > o1 ? o0 : o1;
        if (o2 > loc) loc = o2;
        uint32_t m = __reduce_max_sync(0xffffffffu, loc);
        topv[it] = finv(m);
        int t;
        unsigned b0 = __ballot_sync(0xffffffffu, o0 == m);
        if (b0) t = __ffs(b0) - 1;
        else {
            unsigned b1 = __ballot_sync(0xffffffffu, o1 == m);
            if (b1) t = 32 + __ffs(b1) - 1;
            else {
                unsigned b2 = __ballot_sync(0xffffffffu, o2 == m);
                t = 64 + __ffs(b2) - 1;
            }
        }
        topt[it] = t;
        if ((t & 31) == lane) {
            if (t < 32) o0 = 0u; else if (t < 64) o1 = 0u; else o2 = 0u;
        }
    }

    float outv = 0.f;
    float mx = topv[0];
    if (!(mx == -INFINITY)) {
        float e[TOPM]; float ws = 0.f;
#pragma unroll
        for (int i = 0; i < TOPM; i++) { e[i] = expf(topv[i] - mx); ws += e[i]; }
        float inv = 1.f / ws;
        const float* vb = g_v + (size_t)b * NT * CVD + h * DH + lane;
#pragma unroll
        for (int i = 0; i < TOPM; i++) outv += (e[i] * inv) * vb[(size_t)topt[i] * CVD];
    }
    g_aligned[(size_t)row * CVD + h*DH + lane] = outv;
}

// ---------------- bf16 split helpers ----------------
__device__ __forceinline__ void bf16_split_pack(float x0, float x1, uint32_t& hi, uint32_t& lo) {
    __nv_bfloat16 h0 = __float2bfloat16_rn(x0);
    __nv_bfloat16 h1 = __float2bfloat16_rn(x1);
    __nv_bfloat16 l0 = __float2bfloat16_rn(x0 - __bfloat162float(h0));
    __nv_bfloat16 l1 = __float2bfloat16_rn(x1 - __bfloat162float(h1));
    hi = (uint32_t)__bfloat16_as_ushort(h0) | ((uint32_t)__bfloat16_as_ushort(h1) << 16);
    lo = (uint32_t)__bfloat16_as_ushort(l0) | ((uint32_t)__bfloat16_as_ushort(l1) << 16);
}
__device__ __forceinline__ void mma16(float* c, const uint32_t* a, const uint32_t* b) {
    asm volatile("mma.sync.aligned.m16n8k16.row.col.f32.bf16.bf16.f32 "
        "{%0,%1,%2,%3}, {%4,%5,%6,%7}, {%8,%9}, {%0,%1,%2,%3};"
        : "+f"(c[0]), "+f"(c[1]), "+f"(c[2]), "+f"(c[3])
        : "r"(a[0]), "r"(a[1]), "r"(a[2]), "r"(a[3]), "r"(b[0]), "r"(b[1]));
}
__device__ __forceinline__ void ldsm4(uint32_t* r, uint32_t saddr) {
    asm volatile("ldmatrix.sync.aligned.m8n8.x4.shared.b16 {%0,%1,%2,%3}, [%4];"
        : "=r"(r[0]), "=r"(r[1]), "=r"(r[2]), "=r"(r[3]) : "r"(saddr));
}

// ---------------- split-bf16 GEMM, A fragments via ldmatrix ----------------
// C = A(MxK fp32)@B(KxN fp32) + bias. mode: 0 plain, 1 gelu, 2 per-32col l2norm. res optional.
// Block 128x64, BK=16, 8 warps (4M x 2N), warp 32x32. Double-buffered smem.
// A smem: row-major [m][k-pairs], 12-uint32 (48B) row stride -> LDSM-conflict-free.
#define ASTRIDE 12
__global__ __launch_bounds__(256) void gemm_bf16s_kernel(const float* __restrict__ A,
                                                         const float* __restrict__ B,
                                                         const float* __restrict__ bias,
                                                         const float* __restrict__ res,
                                                         float* __restrict__ C,
                                                         int M, int N, int K, int mode) {
    __shared__ uint32_t AhS[2][128*ASTRIDE], AlS[2][128*ASTRIDE];
    __shared__ uint32_t Bh[2][8][72],  Bl[2][8][72];

    int tid  = threadIdx.x;
    int lane = tid & 31, wid = tid >> 5;
    int warpM = wid & 3, warpN = wid >> 2;
    int g = lane >> 2, t4 = lane & 3;
    int m0 = blockIdx.y * 128, n0 = blockIdx.x * 64;
    int mbase = warpM * 32, nbase = warpN * 32;

    float c[2][4][4];
#pragma unroll
    for (int i = 0; i < 2; i++)
#pragma unroll
        for (int j = 0; j < 4; j++)
#pragma unroll
            for (int l = 0; l < 4; l++) c[i][j][l] = 0.f;

    // A loader: row ar, k-half ha (8 fp32 -> 4 packed pairs -> one 16B store per array)
    int ar   = tid >> 1;
    int ha   = tid & 1;
    int aoff = ar * ASTRIDE + ha * 4;
    // B loader: col bn, pair rows k2b, k2b+1
    int bn   = tid & 63;
    int k2b  = (tid >> 6) * 2;
    const float* Aptr = A + (size_t)(m0 + ar) * K + 8*ha;
    const float* Bptr = B + (size_t)(2*k2b) * N + n0 + bn;

    // ldmatrix source addresses (per mt, per stage computed inside loop)
    int lrow = lane & 15;            // fragment row within 16
    int lkof = (lane >> 4) * 4;      // 0 or 4 uint32 (16B k-offset)

    float4 av0, av1;
    float  b00, b01, b10, b11;
    av0 = *(const float4*)(Aptr);
    av1 = *(const float4*)(Aptr + 4);
    b00 = Bptr[0]; b01 = Bptr[N]; b10 = Bptr[2*N]; b11 = Bptr[3*N];

    // stage tile 0
    {
        uint32_t h0,l0,h1,l1,h2,l2,h3,l3;
        bf16_split_pack(av0.x, av0.y, h0, l0);
        bf16_split_pack(av0.z, av0.w, h1, l1);
        bf16_split_pack(av1.x, av1.y, h2, l2);
        bf16_split_pack(av1.z, av1.w, h3, l3);
        *(uint4*)&AhS[0][aoff] = make_uint4(h0, h1, h2, h3);
        *(uint4*)&AlS[0][aoff] = make_uint4(l0, l1, l2, l3);
        uint32_t h, l;
        bf16_split_pack(b00, b01, h, l); Bh[0][k2b  ][bn] = h; Bl[0][k2b  ][bn] = l;
        bf16_split_pack(b10, b11, h, l); Bh[0][k2b+1][bn] = h; Bl[0][k2b+1][bn] = l;
    }

    int stage = 0;
    for (int k0 = 0; k0 < K; k0 += 16) {
        __syncthreads();
        bool more = (k0 + 16) < K;
        if (more) {
            av0 = *(const float4*)(Aptr + k0 + 16);
            av1 = *(const float4*)(Aptr + k0 + 20);
            const float* bp = Bptr + (size_t)(k0 + 16) * N;
            b00 = bp[0]; b01 = bp[N]; b10 = bp[2*N]; b11 = bp[3*N];
        }

        uint32_t ah[2][4], al[2][4], bh[4][2], blo[4][2];
#pragma unroll
        for (int mt = 0; mt < 2; mt++) {
            int r = mbase + mt*16 + lrow;
            uint32_t addrH = (uint32_t)__cvta_generic_to_shared(&AhS[stage][r*ASTRIDE + lkof]);
            uint32_t addrL = (uint32_t)__cvta_generic_to_shared(&AlS[stage][r*ASTRIDE + lkof]);
            ldsm4(ah[mt], addrH);
            ldsm4(al[mt], addrL);
        }
#pragma unroll
        for (int nt = 0; nt < 4; nt++) {
            int cn = nbase + nt*8 + g;
            bh[nt][0]  = Bh[stage][t4][cn];    bh[nt][1]  = Bh[stage][t4+4][cn];
            blo[nt][0] = Bl[stage][t4][cn];    blo[nt][1] = Bl[stage][t4+4][cn];
        }
#pragma unroll
        for (int mt = 0; mt < 2; mt++)
#pragma unroll
            for (int nt = 0; nt < 4; nt++) {
                mma16(c[mt][nt], al[mt], bh[nt]);
                mma16(c[mt][nt], ah[mt], blo[nt]);
                mma16(c[mt][nt], ah[mt], bh[nt]);
            }

        if (more) {
            int ns = stage ^ 1;
            uint32_t h0,l0,h1,l1,h2,l2,h3,l3;
            bf16_split_pack(av0.x, av0.y, h0, l0);
            bf16_split_pack(av0.z, av0.w, h1, l1);
            bf16_split_pack(av1.x, av1.y, h2, l2);
            bf16_split_pack(av1.z, av1.w, h3, l3);
            *(uint4*)&AhS[ns][aoff] = make_uint4(h0, h1, h2, h3);
            *(uint4*)&AlS[ns][aoff] = make_uint4(l0, l1, l2, l3);
            uint32_t h, l;
            bf16_split_pack(b00, b01, h, l); Bh[ns][k2b  ][bn] = h; Bl[ns][k2b  ][bn] = l;
            bf16_split_pack(b10, b11, h, l); Bh[ns][k2b+1][bn] = h; Bl[ns][k2b+1][bn] = l;
        }
        stage ^= 1;
    }

    // epilogue: bias -> (optional l2norm) -> (optional gelu) -> (optional res) -> store
#pragma unroll
    for (int mt = 0; mt < 2; mt++)
#pragma unroll
        for (int nt = 0; nt < 4; nt++) {
            int col = n0 + nbase + nt*8 + t4*2;
            float b0v = bias[col], b1v = bias[col + 1];
            c[mt][nt][0] += b0v; c[mt][nt][1] += b1v;
            c[mt][nt][2] += b0v; c[mt][nt][3] += b1v;
        }

    if (mode == 2) {
#pragma unroll
        for (int mt = 0; mt < 2; mt++) {
            float ss0 = 0.f, ss1 = 0.f;
#pragma unroll
            for (int nt = 0; nt < 4; nt++) {
                ss0 += c[mt][nt][0]*c[mt][nt][0] + c[mt][nt][1]*c[mt][nt][1];
                ss1 += c[mt][nt][2]*c[mt][nt][2] + c[mt][nt][3]*c[mt][nt][3];
            }
            ss0 += __shfl_xor_sync(~0u, ss0, 1); ss0 += __shfl_xor_sync(~0u, ss0, 2);
            ss1 += __shfl_xor_sync(~0u, ss1, 1); ss1 += __shfl_xor_sync(~0u, ss1, 2);
            float i0 = 1.f / fmaxf(sqrtf(ss0), 1e-6f);
            float i1 = 1.f / fmaxf(sqrtf(ss1), 1e-6f);
#pragma unroll
            for (int nt = 0; nt < 4; nt++) {
                c[mt][nt][0] *= i0; c[mt][nt][1] *= i0;
                c[mt][nt][2] *= i1; c[mt][nt][3] *= i1;
            }
        }
    }

#pragma unroll
    for (int mt = 0; mt < 2; mt++)
#pragma unroll
        for (int nt = 0; nt < 4; nt++) {
            int col = n0 + nbase + nt*8 + t4*2;
            size_t r0 = (size_t)(m0 + mbase + mt*16 + g);
            size_t r1 = r0 + 8;
            float v0 = c[mt][nt][0], v1 = c[mt][nt][1];
            float v2 = c[mt][nt][2], v3 = c[mt][nt][3];
            if (mode == 1) {
                v0 = 0.5f*v0*(1.f + erff(v0*0.70710678118654752f));
                v1 = 0.5f*v1*(1.f + erff(v1*0.70710678118654752f));
                v2 = 0.5f*v2*(1.f + erff(v2*0.70710678118654752f));
                v3 = 0.5f*v3*(1.f + erff(v3*0.70710678118654752f));
            }
            if (res) {
                v0 += res[r0*N + col]; v1 += res[r0*N + col + 1];
                v2 += res[r1*N + col]; v3 += res[r1*N + col + 1];
            }
            *(float2*)&C[r0*N + col] = make_float2(v0, v1);
            *(float2*)&C[r1*N + col] = make_float2(v2, v3);
        }
}

// ---------------- launch ----------------
extern "C" void kernel_launch(void* const* d_in, const int* in_sizes, int n_in,
                              void* d_out, int out_size) {
    const float* vis   = (const float*)d_in[0];
    const float* text  = (const float*)d_in[1];
    const float* Wq    = (const float*)d_in[2];
    const float* bq    = (const float*)d_in[3];
    const float* Wk    = (const float*)d_in[4];
    const float* bk    = (const float*)d_in[5];
    const float* Wv    = (const float*)d_in[6];
    const float* bv    = (const float*)d_in[7];
    const float* Wo    = (const float*)d_in[8];
    const float* bo    = (const float*)d_in[9];
    const float* g1    = (const float*)d_in[10];
    const float* b1    = (const float*)d_in[11];
    const float* g2    = (const float*)d_in[12];
    const float* b2    = (const float*)d_in[13];
    const float* Wf1   = (const float*)d_in[14];
    const float* bf1   = (const float*)d_in[15];
    const float* Wf2   = (const float*)d_in[16];
    const float* bf2   = (const float*)d_in[17];
    const float* ls    = (const float*)d_in[18];
    const float* alpha = (const float*)d_in[19];
    float* out = (float*)d_out;

    float *px, *pq, *paligned, *pproj, *py2, *phdn;
    cudaGetSymbolAddress((void**)&px,       g_x);
    cudaGetSymbolAddress((void**)&pq,       g_q);
    cudaGetSymbolAddress((void**)&paligned, g_aligned);
    cudaGetSymbolAddress((void**)&pproj,    g_proj);
    cudaGetSymbolAddress((void**)&py2,      g_y2);
    cudaGetSymbolAddress((void**)&phdn,     g_hdn);

    ln1_kernel<<<ROWS/8, 256>>>(vis, g1, b1);
    kv_kernel<<<NB*NT, 256>>>(text, Wk, bk, Wv, bv);
    gemm_bf16s_kernel<<<dim3(CVD/64, ROWS/128), 256>>>(px, Wq, bq, nullptr, pq, ROWS, CVD, CVD, 2);
    attn_kernel<<<ROWS, 256>>>(ls);
    gemm_bf16s_kernel<<<dim3(CVD/64, ROWS/128), 256>>>(paligned, Wo, bo, nullptr, pproj, ROWS, CVD, CVD, 0);
    ln2res_kernel<<<ROWS/8, 256>>>(g2, b2, alpha);
    gemm_bf16s_kernel<<<dim3(4*CVD/64, ROWS/128), 256>>>(py2, Wf1, bf1, nullptr, phdn, ROWS, 4*CVD, CVD, 1);
    gemm_bf16s_kernel<<<dim3(CVD/64, ROWS/128), 256>>>(phdn, Wf2, bf2, py2, out, ROWS, CVD, 4*CVD, 0);
}